// round 11
// baseline (speedup 1.0000x reference)
#include <cuda_runtime.h>
#include <cuda_fp16.h>
#include <cstdint>

// ---------------- scratch (static device globals; no allocation) ----------------
__device__ __align__(16) float g_t0[8*128*128*256];  // NHWC fused input L0
__device__ __align__(16) float g_t1[8*64*64*256];    // NHWC fused input L1
__device__ __align__(16) float g_t2[8*32*32*256];    // NHWC fused input L2
__device__ __align__(16) float g_t3[8*16*16*256];    // NHWC x3 L3
__device__ __align__(16) float g_s1[8*256*64*64];    // NCHW fused L1 (offconv)
__device__ __align__(16) float g_s2[8*256*32*32];    // NCHW fused L2 (offconv)
__device__ float  g_offp[8*8*18*64*64];              // c-split offset-conv partials
__device__ float  g_owt[4*2304*18];
__device__ __align__(16) float g_part[8*8*256*256*4]; // K-split partials (33.5MB worth)
__device__ __align__(16) __half g_wh[4*256*2304];    // W hi fp16, [l][o][k*256+c]
__device__ __align__(16) __half g_wl[4*256*2304];    // W lo fp16

__device__ __forceinline__ const float* t_buf(int l) {
    return (l == 0) ? g_t0 : (l == 1 ? g_t1 : (l == 2 ? g_t2 : g_t3));
}
__device__ __forceinline__ const float* s_nchw(const float* ext, int l) {
    if (ext) return ext;
    return (l == 1) ? g_s1 : g_s2;
}

__device__ __forceinline__ uint32_t smem_u32(const void* p) {
    uint32_t a;
    asm("{ .reg .u64 t; cvta.to.shared.u64 t, %1; cvt.u32.u64 %0, t; }" : "=r"(a) : "l"(p));
    return a;
}
__device__ __forceinline__ void cp16(uint32_t d, const void* s) {
    asm volatile("cp.async.cg.shared.global [%0], [%1], 16;" :: "r"(d), "l"(s) : "memory");
}
__device__ __forceinline__ void mma_fp16(float* c, const uint32_t* a, const uint32_t* b) {
    asm volatile(
        "mma.sync.aligned.m16n8k16.row.col.f32.f16.f16.f32 "
        "{%0,%1,%2,%3}, {%4,%5,%6,%7}, {%8,%9}, {%0,%1,%2,%3};"
        : "+f"(c[0]), "+f"(c[1]), "+f"(c[2]), "+f"(c[3])
        : "r"(a[0]), "r"(a[1]), "r"(a[2]), "r"(a[3]), "r"(b[0]), "r"(b[1]));
}
__device__ __forceinline__ void ldsm4(uint32_t a, uint32_t& r0, uint32_t& r1,
                                      uint32_t& r2, uint32_t& r3) {
    asm volatile("ldmatrix.sync.aligned.m8n8.x4.shared.b16 {%0,%1,%2,%3}, [%4];"
                 : "=r"(r0), "=r"(r1), "=r"(r2), "=r"(r3) : "r"(a));
}

// ---------------- weight prep: fp16 hi/lo split, tap-major reorder ----------------
__global__ void k_prep(const float* __restrict__ w, const float* __restrict__ ow) {
    int i = blockIdx.x * blockDim.x + threadIdx.x;
    if (i < 4*256*2304) {
        int ck2 = i % 2304;
        int o   = (i / 2304) & 255;
        int l   = i / (2304*256);
        int k = ck2 >> 8, c = ck2 & 255;
        float v = __ldg(w + ((size_t)((l*256 + o)*256 + c))*9 + k);
        __half h = __float2half_rn(v);
        g_wh[i] = h;
        g_wl[i] = __float2half_rn(v - __half2float(h));
    }
    if (i < 4*2304*18) {
        int o  = i % 18;
        int ck = (i / 18) % 2304;
        int l  = i / (2304*18);
        g_owt[i] = __ldg(ow + ((size_t)(l*18 + o))*2304 + ck);
    }
}

// ---------------- fuse + transpose: NHWC always, NCHW copy for levels 1/2 ----------------
__global__ void k_fuse_t(const float* __restrict__ xin, const float* __restrict__ tprev,
                         int level, int Wc, int HW) {
    __shared__ float tile[32][33];
    int tid = threadIdx.x;
    int p0 = blockIdx.x * 32;
    int c0 = blockIdx.y * 32;
    int b  = blockIdx.z;

    float* nhwc = (float*)t_buf(level);
    float* nchw = (level == 1) ? g_s1 : ((level == 2) ? g_s2 : nullptr);

    int pl = tid & 31, cl = tid >> 5;
#pragma unroll
    for (int j = 0; j < 4; ++j) {
        int c = c0 + cl + 8*j;
        int p = p0 + pl;
        float v = __ldg(xin + ((size_t)(b*256 + c))*HW + p);
        if (tprev) {
            int y = p / Wc, x = p % Wc;
            v += __ldg(tprev + ((size_t)(b*256 + c))*(HW >> 2) + (y >> 1)*(Wc >> 1) + (x >> 1));
        }
        tile[cl + 8*j][pl] = v;
        if (nchw) nchw[((size_t)(b*256 + c))*HW + p] = v;
    }
    __syncthreads();
    int cl2 = tid & 31, pl2 = tid >> 5;
#pragma unroll
    for (int j = 0; j < 4; ++j) {
        int p = p0 + pl2 + 8*j;
        nhwc[((size_t)(b*HW + p))*256 + c0 + cl2] = tile[cl2][pl2 + 8*j];
    }
}

// ---------------- offset conv (NCHW input), C split 8 ways -> partials ----------------
__global__ void k_offconv(const float* __restrict__ s_ext, int level, int Hc, int Wc) {
    int hw = Hc * Wc;
    int i = blockIdx.x * blockDim.x + threadIdx.x;
    if (i >= 8 * hw) return;
    int cs = blockIdx.y;
    int b = i / hw, p = i % hw;
    int y = p / Wc, x = p % Wc;
    const float* s = s_nchw(s_ext, level);

    float2 acc[9];
#pragma unroll
    for (int o = 0; o < 9; ++o) acc[o] = make_float2(0.f, 0.f);

    const float*  sb = s + ((size_t)b*256 + (size_t)cs*32) * hw;
    const float2* wb = (const float2*)(g_owt + (size_t)level*2304*18 + (size_t)cs*32*9*18);

    for (int c = 0; c < 32; ++c) {
        float sv[9];
#pragma unroll
        for (int k = 0; k < 9; ++k) {
            int yy = y + k/3 - 1, xx = x + (k%3) - 1;
            sv[k] = (yy >= 0 && yy < Hc && xx >= 0 && xx < Wc)
                        ? __ldg(sb + (size_t)c*hw + yy*Wc + xx) : 0.f;
        }
        const float2* wr = wb + c * 81;
#pragma unroll
        for (int k = 0; k < 9; ++k) {
            float v = sv[k];
#pragma unroll
            for (int o = 0; o < 9; ++o) {
                float2 w = __ldg(&wr[k*9 + o]);
                acc[o].x += v * w.x;
                acc[o].y += v * w.y;
            }
        }
    }
    size_t base = (size_t)cs * (size_t)(8*18*hw);
#pragma unroll
    for (int o = 0; o < 9; ++o) {
        g_offp[base + ((size_t)(b*18 + 2*o    ))*hw + p] = acc[o].x;
        g_offp[base + ((size_t)(b*18 + 2*o + 1))*hw + p] = acc[o].y;
    }
}

// ---------------- deterministic K-split reduce: out = bias + sum_s part[s] ----------------
__global__ void k_reduce(const float* __restrict__ bias, float* __restrict__ outp,
                         int hw, int S) {
    int n4 = (8*256*hw) >> 2;
    int i = blockIdx.x * blockDim.x + threadIdx.x;
    if (i >= n4) return;
    const float4* p4 = (const float4*)g_part;
    float4 a = p4[i];
    for (int s = 1; s < S; ++s) {
        float4 q = p4[(size_t)s * n4 + i];
        a.x += q.x; a.y += q.y; a.z += q.z; a.w += q.w;
    }
    int oc = ((i << 2) / hw) & 255;
    float bv = __ldg(bias + oc);
    a.x += bv; a.y += bv; a.z += bv; a.w += bv;
    ((float4*)outp)[i] = a;
}

// ---------------- main conv: mma.sync fp16, 2 passes, ldmatrix, fused coef, K-split ----------------
#define WSTRIDE 40960
#define WLO     20480
#define VOFF    81920
#define VSTRIDE 5120
#define COFF    92160
#define CWOFF   101376
#define DSMEM_BYTES 110592

__device__ __forceinline__ void prefetch_w(
    uint32_t sbase, const __half* gwh, const __half* gwl, int tid, int chn)
{
    const char* ph = (const char*)(gwh + (size_t)tid * 2304 + chn * 32);
    const char* pl = (const char*)(gwl + (size_t)tid * 2304 + chn * 32);
    uint32_t dh = sbase + (chn & 1) * WSTRIDE + tid * 80;
#pragma unroll
    for (int u = 0; u < 4; ++u) {
        cp16(dh + u*16,       ph + u*16);
        cp16(dh + WLO + u*16, pl + u*16);
    }
}

__device__ __forceinline__ void gather_chunk(
    char* dsm, const float* __restrict__ sb, int tid, int chn)
{
    const int4*   sIdx = (const int4*)(dsm + COFF);
    const float4* sWgt = (const float4*)(dsm + CWOFF);
    char* Vb = dsm + VOFF + (chn & 1) * VSTRIDE;
    int kn = chn >> 3;
    int c0 = ((chn & 7) << 5) + ((tid & 7) << 2);
    const float* bp = sb + c0;
#pragma unroll
    for (int i = 0; i < 2; ++i) {
        int px = (tid >> 3) + 32 * i;
        int4   id = sIdx[kn*64 + px];
        float4 w  = sWgt[kn*64 + px];
        float4 a = make_float4(0.f, 0.f, 0.f, 0.f);
        if (w.x != 0.f) {
            float4 v = __ldg((const float4*)(bp + id.x));
            a.x += w.x*v.x; a.y += w.x*v.y; a.z += w.x*v.z; a.w += w.x*v.w;
        }
        if (w.y != 0.f) {
            float4 v = __ldg((const float4*)(bp + id.y));
            a.x += w.y*v.x; a.y += w.y*v.y; a.z += w.y*v.z; a.w += w.y*v.w;
        }
        if (w.z != 0.f) {
            float4 v = __ldg((const float4*)(bp + id.z));
            a.x += w.z*v.x; a.y += w.z*v.y; a.z += w.z*v.z; a.w += w.z*v.w;
        }
        if (w.w != 0.f) {
            float4 v = __ldg((const float4*)(bp + id.w));
            a.x += w.w*v.x; a.y += w.w*v.y; a.z += w.w*v.z; a.w += w.w*v.w;
        }
        __half2 h01 = __floats2half2_rn(a.x, a.y);
        __half2 h23 = __floats2half2_rn(a.z, a.w);
        *(uint2*)(Vb + px * 80 + (tid & 7) * 8) =
            make_uint2(*(uint32_t*)&h01, *(uint32_t*)&h23);
    }
}

__global__ __launch_bounds__(256, 2) void k_dconv_mma(
    int level, int has_off, const float* __restrict__ off_b_lvl,
    const float* __restrict__ bias, float* __restrict__ outp, int HW, int Wc,
    int nch, int use_part)
{
    extern __shared__ char dsm[];
    uint32_t sbase = smem_u32(dsm);

    int tid = threadIdx.x;
    int lane = tid & 31, wid = tid >> 5;
    int b  = blockIdx.y;
    int p0 = blockIdx.x * 64;
    int ks0 = blockIdx.z * nch;          // K-split: chunk range [ks0, ks0+nch)
    int warpM = wid & 3, warpN = wid >> 2;
    int ocbase = warpM * 64, nbase = warpN * 32;
    int g = lane >> 2, t = lane & 3;

    const float* sb = t_buf(level) + (size_t)b * HW * 256 + (size_t)p0 * 256;
    const __half* gwh = g_wh + (size_t)level * 256 * 2304;
    const __half* gwl = g_wl + (size_t)level * 256 * 2304;

    prefetch_w(sbase, gwh, gwl, tid, ks0);
    asm volatile("cp.async.commit_group;" ::: "memory");

    // ---- fused coefficient prologue (offreduce + bilinear coef) ----
    int4*   sIdx = (int4*)(dsm + COFF);
    float4* sWgt = (float4*)(dsm + CWOFF);
    float fH = (float)((HW / Wc) - 1), fW = (float)(Wc - 1);
    for (int i = tid; i < 576; i += 256) {
        int k = i >> 6, px = i & 63;
        int p = p0 + px;
        int y = p / Wc, x = p % Wc;
        float dy = 0.f, dx = 0.f;
        if (has_off) {
            dy = __ldg(off_b_lvl + 2*k);
            dx = __ldg(off_b_lvl + 2*k + 1);
            size_t basei  = ((size_t)(b*18 + 2*k))*HW + p;
            size_t stride = (size_t)8*18*HW;
#pragma unroll
            for (int cs = 0; cs < 8; ++cs) {
                dy += g_offp[(size_t)cs*stride + basei];
                dx += g_offp[(size_t)cs*stride + basei + HW];
            }
        }
        float py = (float)(y + k/3 - 1) + dy;
        float px_f = (float)(x + (k%3) - 1) + dx;
        float y0 = floorf(py), x0 = floorf(px_f);
        float ly = py - y0, lx = px_f - x0;
        int id[4]; float wv[4];
#pragma unroll
        for (int q = 0; q < 4; ++q) {
            float yf = y0 + (float)(q >> 1);
            float xf = x0 + (float)(q & 1);
            float wy = (q >> 1) ? ly : 1.f - ly;
            float wx = (q & 1)  ? lx : 1.f - lx;
            bool v = (yf >= 0.f) && (yf <= fH) && (xf >= 0.f) && (xf <= fW);
            float yc = fminf(fmaxf(yf, 0.f), fH);
            float xc = fminf(fmaxf(xf, 0.f), fW);
            id[q] = (((int)yc * Wc + (int)xc) - p0) * 256;   // relative to sb
            wv[q] = v ? wy * wx : 0.f;
        }
        sIdx[i] = make_int4(id[0], id[1], id[2], id[3]);
        sWgt[i] = make_float4(wv[0], wv[1], wv[2], wv[3]);
    }
    __syncthreads();

    gather_chunk(dsm, sb, tid, ks0);
    asm volatile("cp.async.wait_group 0;" ::: "memory");
    __syncthreads();

    float acc[4][4][4];
#pragma unroll
    for (int mt = 0; mt < 4; ++mt)
#pragma unroll
        for (int nt = 0; nt < 4; ++nt)
#pragma unroll
            for (int q = 0; q < 4; ++q) acc[mt][nt][q] = 0.f;

    int laneoff = (lane & 15) * 80 + (lane >> 4) * 16;
    int kend = ks0 + nch;

    for (int ch = ks0; ch < kend; ++ch) {
        uint32_t wb = sbase + (ch & 1) * WSTRIDE;
        uint32_t vb = sbase + VOFF + (ch & 1) * VSTRIDE;

        if (ch + 1 < kend) {
            prefetch_w(sbase, gwh, gwl, tid, ch + 1);
            asm volatile("cp.async.commit_group;" ::: "memory");
            gather_chunk(dsm, sb, tid, ch + 1);
        }

        // ---- mma: 2 ks x (Wh*V then Wl*V), ldmatrix fragment feeds ----
#pragma unroll
        for (int ks = 0; ks < 2; ++ks) {
            int kb = ks*32;
            uint32_t B[4][2];
            {
                uint32_t t0, t1, t2, t3;
                ldsm4(vb + (uint32_t)nbase*80 + laneoff + kb, t0, t1, t2, t3);
                B[0][0] = t0; B[1][0] = t1; B[0][1] = t2; B[1][1] = t3;
                ldsm4(vb + (uint32_t)(nbase + 16)*80 + laneoff + kb, t0, t1, t2, t3);
                B[2][0] = t0; B[3][0] = t1; B[2][1] = t2; B[3][1] = t3;
            }
#pragma unroll
            for (int mt = 0; mt < 4; ++mt) {
                uint32_t A[4];
                ldsm4(wb + (uint32_t)(ocbase + mt*16)*80 + laneoff + kb,
                      A[0], A[1], A[2], A[3]);
#pragma unroll
                for (int nt = 0; nt < 4; ++nt)
                    mma_fp16(acc[mt][nt], A, B[nt]);
            }
#pragma unroll
            for (int mt = 0; mt < 4; ++mt) {
                uint32_t A[4];
                ldsm4(wb + WLO + (uint32_t)(ocbase + mt*16)*80 + laneoff + kb,
                      A[0], A[1], A[2], A[3]);
#pragma unroll
                for (int nt = 0; nt < 4; ++nt)
                    mma_fp16(acc[mt][nt], A, B[nt]);
            }
        }
        asm volatile("cp.async.wait_group 0;" ::: "memory");
        __syncthreads();
    }

    // ---- epilogue ----
    if (use_part) {
        float* pp = g_part + (size_t)blockIdx.z * 8 * 256 * HW;
#pragma unroll
        for (int mt = 0; mt < 4; ++mt) {
            int oc = ocbase + mt*16 + g;
            float* r0 = pp + ((size_t)(b*256 + oc    ))*HW + p0 + nbase + 2*t;
            float* r1 = pp + ((size_t)(b*256 + oc + 8))*HW + p0 + nbase + 2*t;
#pragma unroll
            for (int nt = 0; nt < 4; ++nt) {
                *(float2*)(r0 + nt*8) = make_float2(acc[mt][nt][0], acc[mt][nt][1]);
                *(float2*)(r1 + nt*8) = make_float2(acc[mt][nt][2], acc[mt][nt][3]);
            }
        }
    } else {
#pragma unroll
        for (int mt = 0; mt < 4; ++mt) {
            int oc = ocbase + mt*16 + g;
            float b0 = __ldg(bias + oc);
            float b1 = __ldg(bias + oc + 8);
            float* r0 = outp + ((size_t)(b*256 + oc    ))*HW + p0 + nbase + 2*t;
            float* r1 = outp + ((size_t)(b*256 + oc + 8))*HW + p0 + nbase + 2*t;
#pragma unroll
            for (int nt = 0; nt < 4; ++nt) {
                float2 u0 = make_float2(acc[mt][nt][0] + b0, acc[mt][nt][1] + b0);
                float2 u1 = make_float2(acc[mt][nt][2] + b1, acc[mt][nt][3] + b1);
                *(float2*)(r0 + nt*8) = u0;
                *(float2*)(r1 + nt*8) = u1;
            }
        }
    }
}

// ---------------- host side ----------------
static inline int divup(int a, int b) { return (a + b - 1) / b; }

extern "C" void kernel_launch(void* const* d_in, const int* in_sizes, int n_in,
                              void* d_out, int out_size) {
    const float* x0      = (const float*)d_in[0];
    const float* x1      = (const float*)d_in[1];
    const float* x2      = (const float*)d_in[2];
    const float* x3      = (const float*)d_in[3];
    const float* weights = (const float*)d_in[4];
    const float* biases  = (const float*)d_in[5];
    const float* off_w   = (const float*)d_in[6];
    const float* off_b   = (const float*)d_in[7];
    float* out = (float*)d_out;

    const size_t T0 = 0;
    const size_t T1 = 33554432;
    const size_t T2 = 41943040;
    const size_t T3 = 44040192;

    (void)in_sizes; (void)n_in; (void)out_size;

    cudaFuncSetAttribute(k_dconv_mma, cudaFuncAttributeMaxDynamicSharedMemorySize, DSMEM_BYTES);

    k_prep<<<divup(4*256*2304, 256), 256>>>(weights, off_w);

    // ---- level 3 (16x16): K-split 8 -> 256 blocks, 9 chunks each ----
    {
        int H = 16, W = 16, hw = 256, S = 8;
        k_fuse_t<<<dim3(hw/32, 8, 8), 256>>>(x3, nullptr, 3, W, hw);
        k_offconv<<<dim3(divup(8*hw, 128), 8), 128>>>(x3, 3, H, W);
        k_dconv_mma<<<dim3(hw/64, 8, S), 256, DSMEM_BYTES>>>(3, 1, off_b + 3*18,
                                                             nullptr, nullptr, hw, W, 72/S, 1);
        k_reduce<<<divup(8*256*hw/4, 256), 256>>>(biases + 3*256, out + T3, hw, S);
    }
    // ---- level 2 (32x32): K-split 4 -> 512 blocks, 18 chunks each ----
    {
        int H = 32, W = 32, hw = 1024, S = 4;
        k_fuse_t<<<dim3(hw/32, 8, 8), 256>>>(x2, out + T3, 2, W, hw);
        k_offconv<<<dim3(divup(8*hw, 128), 8), 128>>>(nullptr, 2, H, W);
        k_dconv_mma<<<dim3(hw/64, 8, S), 256, DSMEM_BYTES>>>(2, 1, off_b + 2*18,
                                                             nullptr, nullptr, hw, W, 72/S, 1);
        k_reduce<<<divup(8*256*hw/4, 256), 256>>>(biases + 2*256, out + T2, hw, S);
    }
    // ---- level 1 (64x64): no split (512 blocks) ----
    {
        int H = 64, W = 64, hw = 4096;
        k_fuse_t<<<dim3(hw/32, 8, 8), 256>>>(x1, out + T2, 1, W, hw);
        k_offconv<<<dim3(divup(8*hw, 128), 8), 128>>>(nullptr, 1, H, W);
        k_dconv_mma<<<dim3(hw/64, 8, 1), 256, DSMEM_BYTES>>>(1, 1, off_b + 1*18,
                                                             biases + 256, out + T1, hw, W, 72, 0);
    }
    // ---- level 0 (128x128): plain conv, no split (2048 blocks) ----
    {
        int H = 128, W = 128, hw = 16384;
        k_fuse_t<<<dim3(hw/32, 8, 8), 256>>>(x0, out + T1, 0, W, hw);
        k_dconv_mma<<<dim3(hw/64, 8, 1), 256, DSMEM_BYTES>>>(0, 0, nullptr,
                                                             biases, out + T0, hw, W, 72, 0);
    }
}

// round 13
// speedup vs baseline: 1.5280x; 1.5280x over previous
#include <cuda_runtime.h>
#include <cuda_fp16.h>
#include <cstdint>

// ---------------- scratch (static device globals; no allocation) ----------------
__device__ __align__(16) float g_t0[8*128*128*256];  // NHWC fused input L0
__device__ __align__(16) float g_t1[8*64*64*256];    // NHWC fused input L1
__device__ __align__(16) float g_t2[8*32*32*256];    // NHWC fused input L2
__device__ __align__(16) float g_t3[8*16*16*256];    // NHWC x3 L3
__device__ __align__(16) float g_s1[8*256*64*64];    // NCHW fused L1 (offconv)
__device__ __align__(16) float g_s2[8*256*32*32];    // NCHW fused L2 (offconv)
__device__ float  g_offp[8*8*18*64*64];              // c-split offset-conv partials
__device__ float  g_owt[4*2304*18];
__device__ __align__(16) float g_part[8*8*256*256*4]; // K-split partials
__device__ __align__(16) __half g_wh[4*256*2304];    // W hi fp16, [l][o][k*256+c]
__device__ __align__(16) __half g_wl[4*256*2304];    // W lo fp16

__device__ __forceinline__ const float* t_buf(int l) {
    return (l == 0) ? g_t0 : (l == 1 ? g_t1 : (l == 2 ? g_t2 : g_t3));
}
__device__ __forceinline__ const float* s_nchw(const float* ext, int l) {
    if (ext) return ext;
    return (l == 1) ? g_s1 : g_s2;
}

__device__ __forceinline__ uint32_t smem_u32(const void* p) {
    uint32_t a;
    asm("{ .reg .u64 t; cvta.to.shared.u64 t, %1; cvt.u32.u64 %0, t; }" : "=r"(a) : "l"(p));
    return a;
}
__device__ __forceinline__ void cp16(uint32_t d, const void* s) {
    asm volatile("cp.async.cg.shared.global [%0], [%1], 16;" :: "r"(d), "l"(s) : "memory");
}
__device__ __forceinline__ void mma_fp16(float* c, const uint32_t* a, const uint32_t* b) {
    asm volatile(
        "mma.sync.aligned.m16n8k16.row.col.f32.f16.f16.f32 "
        "{%0,%1,%2,%3}, {%4,%5,%6,%7}, {%8,%9}, {%0,%1,%2,%3};"
        : "+f"(c[0]), "+f"(c[1]), "+f"(c[2]), "+f"(c[3])
        : "r"(a[0]), "r"(a[1]), "r"(a[2]), "r"(a[3]), "r"(b[0]), "r"(b[1]));
}
__device__ __forceinline__ void ldsm4(uint32_t a, uint32_t& r0, uint32_t& r1,
                                      uint32_t& r2, uint32_t& r3) {
    asm volatile("ldmatrix.sync.aligned.m8n8.x4.shared.b16 {%0,%1,%2,%3}, [%4];"
                 : "=r"(r0), "=r"(r1), "=r"(r2), "=r"(r3) : "r"(a));
}

// ---------------- weight prep: fp16 hi/lo split, tap-major reorder ----------------
__global__ void k_prep(const float* __restrict__ w, const float* __restrict__ ow) {
    int i = blockIdx.x * blockDim.x + threadIdx.x;
    if (i < 4*256*2304) {
        int ck2 = i % 2304;
        int o   = (i / 2304) & 255;
        int l   = i / (2304*256);
        int k = ck2 >> 8, c = ck2 & 255;
        float v = __ldg(w + ((size_t)((l*256 + o)*256 + c))*9 + k);
        __half h = __float2half_rn(v);
        g_wh[i] = h;
        g_wl[i] = __float2half_rn(v - __half2float(h));
    }
    if (i < 4*2304*18) {
        int o  = i % 18;
        int ck = (i / 18) % 2304;
        int l  = i / (2304*18);
        g_owt[i] = __ldg(ow + ((size_t)(l*18 + o))*2304 + ck);
    }
}

// ---------------- fuse + transpose: NHWC always, NCHW copy for levels 1/2 ----------------
__global__ void k_fuse_t(const float* __restrict__ xin, const float* __restrict__ tprev,
                         int level, int Wc, int HW) {
    __shared__ float tile[32][33];
    int tid = threadIdx.x;
    int p0 = blockIdx.x * 32;
    int c0 = blockIdx.y * 32;
    int b  = blockIdx.z;

    float* nhwc = (float*)t_buf(level);
    float* nchw = (level == 1) ? g_s1 : ((level == 2) ? g_s2 : nullptr);

    int pl = tid & 31, cl = tid >> 5;
#pragma unroll
    for (int j = 0; j < 4; ++j) {
        int c = c0 + cl + 8*j;
        int p = p0 + pl;
        float v = __ldg(xin + ((size_t)(b*256 + c))*HW + p);
        if (tprev) {
            int y = p / Wc, x = p % Wc;
            v += __ldg(tprev + ((size_t)(b*256 + c))*(HW >> 2) + (y >> 1)*(Wc >> 1) + (x >> 1));
        }
        tile[cl + 8*j][pl] = v;
        if (nchw) nchw[((size_t)(b*256 + c))*HW + p] = v;
    }
    __syncthreads();
    int cl2 = tid & 31, pl2 = tid >> 5;
#pragma unroll
    for (int j = 0; j < 4; ++j) {
        int p = p0 + pl2 + 8*j;
        nhwc[((size_t)(b*HW + p))*256 + c0 + cl2] = tile[cl2][pl2 + 8*j];
    }
}

// ---------------- offset conv (NCHW input), C split 8 ways -> partials ----------------
__global__ void k_offconv(const float* __restrict__ s_ext, int level, int Hc, int Wc) {
    int hw = Hc * Wc;
    int i = blockIdx.x * blockDim.x + threadIdx.x;
    if (i >= 8 * hw) return;
    int cs = blockIdx.y;
    int b = i / hw, p = i % hw;
    int y = p / Wc, x = p % Wc;
    const float* s = s_nchw(s_ext, level);

    float2 acc[9];
#pragma unroll
    for (int o = 0; o < 9; ++o) acc[o] = make_float2(0.f, 0.f);

    const float*  sb = s + ((size_t)b*256 + (size_t)cs*32) * hw;
    const float2* wb = (const float2*)(g_owt + (size_t)level*2304*18 + (size_t)cs*32*9*18);

    for (int c = 0; c < 32; ++c) {
        float sv[9];
#pragma unroll
        for (int k = 0; k < 9; ++k) {
            int yy = y + k/3 - 1, xx = x + (k%3) - 1;
            sv[k] = (yy >= 0 && yy < Hc && xx >= 0 && xx < Wc)
                        ? __ldg(sb + (size_t)c*hw + yy*Wc + xx) : 0.f;
        }
        const float2* wr = wb + c * 81;
#pragma unroll
        for (int k = 0; k < 9; ++k) {
            float v = sv[k];
#pragma unroll
            for (int o = 0; o < 9; ++o) {
                float2 w = __ldg(&wr[k*9 + o]);
                acc[o].x += v * w.x;
                acc[o].y += v * w.y;
            }
        }
    }
    size_t base = (size_t)cs * (size_t)(8*18*hw);
#pragma unroll
    for (int o = 0; o < 9; ++o) {
        g_offp[base + ((size_t)(b*18 + 2*o    ))*hw + p] = acc[o].x;
        g_offp[base + ((size_t)(b*18 + 2*o + 1))*hw + p] = acc[o].y;
    }
}

// ---------------- deterministic K-split reduce: out = bias + sum_s part[s] ----------------
__global__ void k_reduce(const float* __restrict__ bias, float* __restrict__ outp,
                         int hw, int S) {
    int n4 = (8*256*hw) >> 2;
    int i = blockIdx.x * blockDim.x + threadIdx.x;
    if (i >= n4) return;
    const float4* p4 = (const float4*)g_part;
    float4 a = p4[i];
    for (int s = 1; s < S; ++s) {
        float4 q = p4[(size_t)s * n4 + i];
        a.x += q.x; a.y += q.y; a.z += q.z; a.w += q.w;
    }
    int oc = ((i << 2) / hw) & 255;
    float bv = __ldg(bias + oc);
    a.x += bv; a.y += bv; a.z += bv; a.w += bv;
    ((float4*)outp)[i] = a;
}

// ---------------- main conv: mma.sync fp16, latency-hiding gather split ----------------
#define WSTRIDE 40960
#define WLO     20480
#define VOFF    81920
#define VSTRIDE 5120
#define COFF    92160
#define CWOFF   101376
#define DSMEM_BYTES 110592

__device__ __forceinline__ void prefetch_w(
    uint32_t sbase, const __half* gwh, const __half* gwl, int tid, int chn)
{
    const char* ph = (const char*)(gwh + (size_t)tid * 2304 + chn * 32);
    const char* pl = (const char*)(gwl + (size_t)tid * 2304 + chn * 32);
    uint32_t dh = sbase + (chn & 1) * WSTRIDE + tid * 80;
#pragma unroll
    for (int u = 0; u < 4; ++u) {
        cp16(dh + u*16,       ph + u*16);
        cp16(dh + WLO + u*16, pl + u*16);
    }
}

// staged gather: load phase (LDGs only, results held in regs) + store phase (after mma)
struct GStage {
    float4 v0, v1, v2, v3;
    float4 w;
    int px;
};

__device__ __forceinline__ void gather_load(
    const char* dsm, const float* __restrict__ sb, int tid, int chn, int iter, GStage& s)
{
    const int4*   sIdx = (const int4*)(dsm + COFF);
    const float4* sWgt = (const float4*)(dsm + CWOFF);
    int kn = chn >> 3;
    const float* bp = sb + ((chn & 7) << 5) + ((tid & 7) << 2);
    s.px = (tid >> 3) + 32 * iter;
    int4 id = sIdx[kn*64 + s.px];
    s.w = sWgt[kn*64 + s.px];
    s.v0 = make_float4(0.f, 0.f, 0.f, 0.f);
    s.v1 = s.v0; s.v2 = s.v0; s.v3 = s.v0;
    if (s.w.x != 0.f) s.v0 = __ldg((const float4*)(bp + id.x));
    if (s.w.y != 0.f) s.v1 = __ldg((const float4*)(bp + id.y));
    if (s.w.z != 0.f) s.v2 = __ldg((const float4*)(bp + id.z));
    if (s.w.w != 0.f) s.v3 = __ldg((const float4*)(bp + id.w));
}

__device__ __forceinline__ void gather_store(
    char* dsm, int tid, int chn, const GStage& s)
{
    char* Vb = dsm + VOFF + (chn & 1) * VSTRIDE;
    float4 a;
    a.x = s.w.x*s.v0.x + s.w.y*s.v1.x + s.w.z*s.v2.x + s.w.w*s.v3.x;
    a.y = s.w.x*s.v0.y + s.w.y*s.v1.y + s.w.z*s.v2.y + s.w.w*s.v3.y;
    a.z = s.w.x*s.v0.z + s.w.y*s.v1.z + s.w.z*s.v2.z + s.w.w*s.v3.z;
    a.w = s.w.x*s.v0.w + s.w.y*s.v1.w + s.w.z*s.v2.w + s.w.w*s.v3.w;
    __half2 h01 = __floats2half2_rn(a.x, a.y);
    __half2 h23 = __floats2half2_rn(a.z, a.w);
    *(uint2*)(Vb + s.px * 80 + (tid & 7) * 8) =
        make_uint2(*(uint32_t*)&h01, *(uint32_t*)&h23);
}

__global__ __launch_bounds__(256, 2) void k_dconv_mma(
    int level, int has_off, const float* __restrict__ off_b_lvl,
    const float* __restrict__ bias, float* __restrict__ outp, int HW, int Wc,
    int nch, int use_part)
{
    extern __shared__ char dsm[];
    uint32_t sbase = smem_u32(dsm);

    int tid = threadIdx.x;
    int lane = tid & 31, wid = tid >> 5;
    int b  = blockIdx.y;
    int p0 = blockIdx.x * 64;
    int ks0 = blockIdx.z * nch;
    int warpM = wid & 3, warpN = wid >> 2;
    int ocbase = warpM * 64, nbase = warpN * 32;
    int g = lane >> 2, t = lane & 3;

    const float* sb = t_buf(level) + (size_t)b * HW * 256 + (size_t)p0 * 256;
    const __half* gwh = g_wh + (size_t)level * 256 * 2304;
    const __half* gwl = g_wl + (size_t)level * 256 * 2304;

    prefetch_w(sbase, gwh, gwl, tid, ks0);
    asm volatile("cp.async.commit_group;" ::: "memory");

    // ---- fused coefficient prologue (offreduce + bilinear coef) ----
    int4*   sIdx = (int4*)(dsm + COFF);
    float4* sWgt = (float4*)(dsm + CWOFF);
    float fH = (float)((HW / Wc) - 1), fW = (float)(Wc - 1);
    for (int i = tid; i < 576; i += 256) {
        int k = i >> 6, px = i & 63;
        int p = p0 + px;
        int y = p / Wc, x = p % Wc;
        float dy = 0.f, dx = 0.f;
        if (has_off) {
            dy = __ldg(off_b_lvl + 2*k);
            dx = __ldg(off_b_lvl + 2*k + 1);
            size_t basei  = ((size_t)(b*18 + 2*k))*HW + p;
            size_t stride = (size_t)8*18*HW;
#pragma unroll
            for (int cs = 0; cs < 8; ++cs) {
                dy += g_offp[(size_t)cs*stride + basei];
                dx += g_offp[(size_t)cs*stride + basei + HW];
            }
        }
        float py = (float)(y + k/3 - 1) + dy;
        float px_f = (float)(x + (k%3) - 1) + dx;
        float y0 = floorf(py), x0 = floorf(px_f);
        float ly = py - y0, lx = px_f - x0;
        int id[4]; float wv[4];
#pragma unroll
        for (int q = 0; q < 4; ++q) {
            float yf = y0 + (float)(q >> 1);
            float xf = x0 + (float)(q & 1);
            float wy = (q >> 1) ? ly : 1.f - ly;
            float wx = (q & 1)  ? lx : 1.f - lx;
            bool v = (yf >= 0.f) && (yf <= fH) && (xf >= 0.f) && (xf <= fW);
            float yc = fminf(fmaxf(yf, 0.f), fH);
            float xc = fminf(fmaxf(xf, 0.f), fW);
            id[q] = (((int)yc * Wc + (int)xc) - p0) * 256;   // relative to sb
            wv[q] = v ? wy * wx : 0.f;
        }
        sIdx[i] = make_int4(id[0], id[1], id[2], id[3]);
        sWgt[i] = make_float4(wv[0], wv[1], wv[2], wv[3]);
    }
    __syncthreads();

    // prologue gather for first chunk
    {
        GStage s0, s1;
        gather_load((const char*)dsm, sb, tid, ks0, 0, s0);
        gather_load((const char*)dsm, sb, tid, ks0, 1, s1);
        gather_store(dsm, tid, ks0, s0);
        gather_store(dsm, tid, ks0, s1);
    }
    asm volatile("cp.async.wait_group 0;" ::: "memory");
    __syncthreads();

    float acc[4][4][4];
#pragma unroll
    for (int mt = 0; mt < 4; ++mt)
#pragma unroll
        for (int nt = 0; nt < 4; ++nt)
#pragma unroll
            for (int q = 0; q < 4; ++q) acc[mt][nt][q] = 0.f;

    int laneoff = (lane & 15) * 80 + (lane >> 4) * 16;
    int kend = ks0 + nch;

    for (int ch = ks0; ch < kend; ++ch) {
        uint32_t wb = sbase + (ch & 1) * WSTRIDE;
        uint32_t vb = sbase + VOFF + (ch & 1) * VSTRIDE;
        bool pre = (ch + 1 < kend);

        if (pre) prefetch_w(sbase, gwh, gwl, tid, ch + 1);
        asm volatile("cp.async.commit_group;" ::: "memory");

        GStage st;
        if (pre) gather_load((const char*)dsm, sb, tid, ch + 1, 0, st);

        // ---- mma ks=0 (LDG latency for iter0 hides under these 64 HMMA) ----
        {
            int kb = 0;
            uint32_t B[4][2];
            {
                uint32_t t0, t1, t2, t3;
                ldsm4(vb + (uint32_t)nbase*80 + laneoff + kb, t0, t1, t2, t3);
                B[0][0] = t0; B[1][0] = t1; B[0][1] = t2; B[1][1] = t3;
                ldsm4(vb + (uint32_t)(nbase + 16)*80 + laneoff + kb, t0, t1, t2, t3);
                B[2][0] = t0; B[3][0] = t1; B[2][1] = t2; B[3][1] = t3;
            }
#pragma unroll
            for (int mt = 0; mt < 4; ++mt) {
                uint32_t A[4];
                ldsm4(wb + (uint32_t)(ocbase + mt*16)*80 + laneoff + kb,
                      A[0], A[1], A[2], A[3]);
#pragma unroll
                for (int nt = 0; nt < 4; ++nt)
                    mma_fp16(acc[mt][nt], A, B[nt]);
            }
#pragma unroll
            for (int mt = 0; mt < 4; ++mt) {
                uint32_t A[4];
                ldsm4(wb + WLO + (uint32_t)(ocbase + mt*16)*80 + laneoff + kb,
                      A[0], A[1], A[2], A[3]);
#pragma unroll
                for (int nt = 0; nt < 4; ++nt)
                    mma_fp16(acc[mt][nt], A, B[nt]);
            }
        }

        if (pre) {
            gather_store(dsm, tid, ch + 1, st);
            gather_load((const char*)dsm, sb, tid, ch + 1, 1, st);
        }

        // ---- mma ks=1 (hides iter1 LDG latency) ----
        {
            int kb = 32;
            uint32_t B[4][2];
            {
                uint32_t t0, t1, t2, t3;
                ldsm4(vb + (uint32_t)nbase*80 + laneoff + kb, t0, t1, t2, t3);
                B[0][0] = t0; B[1][0] = t1; B[0][1] = t2; B[1][1] = t3;
                ldsm4(vb + (uint32_t)(nbase + 16)*80 + laneoff + kb, t0, t1, t2, t3);
                B[2][0] = t0; B[3][0] = t1; B[2][1] = t2; B[3][1] = t3;
            }
#pragma unroll
            for (int mt = 0; mt < 4; ++mt) {
                uint32_t A[4];
                ldsm4(wb + (uint32_t)(ocbase + mt*16)*80 + laneoff + kb,
                      A[0], A[1], A[2], A[3]);
#pragma unroll
                for (int nt = 0; nt < 4; ++nt)
                    mma_fp16(acc[mt][nt], A, B[nt]);
            }
#pragma unroll
            for (int mt = 0; mt < 4; ++mt) {
                uint32_t A[4];
                ldsm4(wb + WLO + (uint32_t)(ocbase + mt*16)*80 + laneoff + kb,
                      A[0], A[1], A[2], A[3]);
#pragma unroll
                for (int nt = 0; nt < 4; ++nt)
                    mma_fp16(acc[mt][nt], A, B[nt]);
            }
        }

        if (pre) gather_store(dsm, tid, ch + 1, st);

        asm volatile("cp.async.wait_group 0;" ::: "memory");
        __syncthreads();
    }

    // ---- epilogue ----
    if (use_part) {
        float* pp = g_part + (size_t)blockIdx.z * 8 * 256 * HW;
#pragma unroll
        for (int mt = 0; mt < 4; ++mt) {
            int oc = ocbase + mt*16 + g;
            float* r0 = pp + ((size_t)(b*256 + oc    ))*HW + p0 + nbase + 2*t;
            float* r1 = pp + ((size_t)(b*256 + oc + 8))*HW + p0 + nbase + 2*t;
#pragma unroll
            for (int nt = 0; nt < 4; ++nt) {
                *(float2*)(r0 + nt*8) = make_float2(acc[mt][nt][0], acc[mt][nt][1]);
                *(float2*)(r1 + nt*8) = make_float2(acc[mt][nt][2], acc[mt][nt][3]);
            }
        }
    } else {
#pragma unroll
        for (int mt = 0; mt < 4; ++mt) {
            int oc = ocbase + mt*16 + g;
            float b0 = __ldg(bias + oc);
            float b1 = __ldg(bias + oc + 8);
            float* r0 = outp + ((size_t)(b*256 + oc    ))*HW + p0 + nbase + 2*t;
            float* r1 = outp + ((size_t)(b*256 + oc + 8))*HW + p0 + nbase + 2*t;
#pragma unroll
            for (int nt = 0; nt < 4; ++nt) {
                float2 u0 = make_float2(acc[mt][nt][0] + b0, acc[mt][nt][1] + b0);
                float2 u1 = make_float2(acc[mt][nt][2] + b1, acc[mt][nt][3] + b1);
                *(float2*)(r0 + nt*8) = u0;
                *(float2*)(r1 + nt*8) = u1;
            }
        }
    }
}

// ---------------- host side ----------------
static inline int divup(int a, int b) { return (a + b - 1) / b; }

extern "C" void kernel_launch(void* const* d_in, const int* in_sizes, int n_in,
                              void* d_out, int out_size) {
    const float* x0      = (const float*)d_in[0];
    const float* x1      = (const float*)d_in[1];
    const float* x2      = (const float*)d_in[2];
    const float* x3      = (const float*)d_in[3];
    const float* weights = (const float*)d_in[4];
    const float* biases  = (const float*)d_in[5];
    const float* off_w   = (const float*)d_in[6];
    const float* off_b   = (const float*)d_in[7];
    float* out = (float*)d_out;

    const size_t T0 = 0;
    const size_t T1 = 33554432;
    const size_t T2 = 41943040;
    const size_t T3 = 44040192;

    (void)in_sizes; (void)n_in; (void)out_size;

    cudaFuncSetAttribute(k_dconv_mma, cudaFuncAttributeMaxDynamicSharedMemorySize, DSMEM_BYTES);

    k_prep<<<divup(4*256*2304, 256), 256>>>(weights, off_w);

    // ---- level 3 (16x16): K-split 8 -> 256 blocks, 9 chunks each ----
    {
        int H = 16, W = 16, hw = 256, S = 8;
        k_fuse_t<<<dim3(hw/32, 8, 8), 256>>>(x3, nullptr, 3, W, hw);
        k_offconv<<<dim3(divup(8*hw, 128), 8), 128>>>(x3, 3, H, W);
        k_dconv_mma<<<dim3(hw/64, 8, S), 256, DSMEM_BYTES>>>(3, 1, off_b + 3*18,
                                                             nullptr, nullptr, hw, W, 72/S, 1);
        k_reduce<<<divup(8*256*hw/4, 256), 256>>>(biases + 3*256, out + T3, hw, S);
    }
    // ---- level 2 (32x32): K-split 4 -> 512 blocks, 18 chunks each ----
    {
        int H = 32, W = 32, hw = 1024, S = 4;
        k_fuse_t<<<dim3(hw/32, 8, 8), 256>>>(x2, out + T3, 2, W, hw);
        k_offconv<<<dim3(divup(8*hw, 128), 8), 128>>>(nullptr, 2, H, W);
        k_dconv_mma<<<dim3(hw/64, 8, S), 256, DSMEM_BYTES>>>(2, 1, off_b + 2*18,
                                                             nullptr, nullptr, hw, W, 72/S, 1);
        k_reduce<<<divup(8*256*hw/4, 256), 256>>>(biases + 2*256, out + T2, hw, S);
    }
    // ---- level 1 (64x64): no split (512 blocks) ----
    {
        int H = 64, W = 64, hw = 4096;
        k_fuse_t<<<dim3(hw/32, 8, 8), 256>>>(x1, out + T2, 1, W, hw);
        k_offconv<<<dim3(divup(8*hw, 128), 8), 128>>>(nullptr, 1, H, W);
        k_dconv_mma<<<dim3(hw/64, 8, 1), 256, DSMEM_BYTES>>>(1, 1, off_b + 1*18,
                                                             biases + 256, out + T1, hw, W, 72, 0);
    }
    // ---- level 0 (128x128): plain conv, no split (2048 blocks) ----
    {
        int H = 128, W = 128, hw = 16384;
        k_fuse_t<<<dim3(hw/32, 8, 8), 256>>>(x0, out + T1, 0, W, hw);
        k_dconv_mma<<<dim3(hw/64, 8, 1), 256, DSMEM_BYTES>>>(0, 0, nullptr,
                                                             biases, out + T0, hw, W, 72, 0);
    }
}

// round 14
// speedup vs baseline: 2.3849x; 1.5608x over previous
#include <cuda_runtime.h>
#include <cuda_fp16.h>
#include <cstdint>

// ---------------- scratch (static device globals; no allocation) ----------------
__device__ __align__(16) float g_t0[8*128*128*256];  // NHWC fused input L0
__device__ __align__(16) float g_t1[8*64*64*256];    // NHWC fused input L1
__device__ __align__(16) float g_t2[8*32*32*256];    // NHWC fused input L2
__device__ __align__(16) float g_t3[8*16*16*256];    // NHWC x3 L3
__device__ __align__(16) float g_s1[8*256*64*64];    // NCHW fused L1 (offconv)
__device__ __align__(16) float g_s2[8*256*32*32];    // NCHW fused L2 (offconv)
__device__ float  g_offp[8*8*18*64*64];              // c-split offset-conv partials
__device__ float  g_owt[4*2304*18];
__device__ __align__(16) float g_part[8*8*256*256*4]; // K-split partials
__device__ __align__(16) __half g_w[4*256*2304];     // W fp16, [l][o][k*256+c]

__device__ __forceinline__ const float* t_buf(int l) {
    return (l == 0) ? g_t0 : (l == 1 ? g_t1 : (l == 2 ? g_t2 : g_t3));
}
__device__ __forceinline__ const float* s_nchw(const float* ext, int l) {
    if (ext) return ext;
    return (l == 1) ? g_s1 : g_s2;
}

__device__ __forceinline__ uint32_t smem_u32(const void* p) {
    uint32_t a;
    asm("{ .reg .u64 t; cvta.to.shared.u64 t, %1; cvt.u32.u64 %0, t; }" : "=r"(a) : "l"(p));
    return a;
}
__device__ __forceinline__ void cp16(uint32_t d, const void* s) {
    asm volatile("cp.async.cg.shared.global [%0], [%1], 16;" :: "r"(d), "l"(s) : "memory");
}
__device__ __forceinline__ void mma_fp16(float* c, const uint32_t* a, const uint32_t* b) {
    asm volatile(
        "mma.sync.aligned.m16n8k16.row.col.f32.f16.f16.f32 "
        "{%0,%1,%2,%3}, {%4,%5,%6,%7}, {%8,%9}, {%0,%1,%2,%3};"
        : "+f"(c[0]), "+f"(c[1]), "+f"(c[2]), "+f"(c[3])
        : "r"(a[0]), "r"(a[1]), "r"(a[2]), "r"(a[3]), "r"(b[0]), "r"(b[1]));
}
__device__ __forceinline__ void ldsm4(uint32_t a, uint32_t& r0, uint32_t& r1,
                                      uint32_t& r2, uint32_t& r3) {
    asm volatile("ldmatrix.sync.aligned.m8n8.x4.shared.b16 {%0,%1,%2,%3}, [%4];"
                 : "=r"(r0), "=r"(r1), "=r"(r2), "=r"(r3) : "r"(a));
}

// ---------------- weight prep: fp16 convert, tap-major reorder ----------------
__global__ void k_prep(const float* __restrict__ w, const float* __restrict__ ow) {
    int i = blockIdx.x * blockDim.x + threadIdx.x;
    if (i < 4*256*2304) {
        int ck2 = i % 2304;
        int o   = (i / 2304) & 255;
        int l   = i / (2304*256);
        int k = ck2 >> 8, c = ck2 & 255;
        float v = __ldg(w + ((size_t)((l*256 + o)*256 + c))*9 + k);
        g_w[i] = __float2half_rn(v);
    }
    if (i < 4*2304*18) {
        int o  = i % 18;
        int ck = (i / 18) % 2304;
        int l  = i / (2304*18);
        g_owt[i] = __ldg(ow + ((size_t)(l*18 + o))*2304 + ck);
    }
}

// ---------------- fuse + transpose: NHWC always, NCHW copy for levels 1/2 ----------------
__global__ void k_fuse_t(const float* __restrict__ xin, const float* __restrict__ tprev,
                         int level, int Wc, int HW) {
    __shared__ float tile[32][33];
    int tid = threadIdx.x;
    int p0 = blockIdx.x * 32;
    int c0 = blockIdx.y * 32;
    int b  = blockIdx.z;

    float* nhwc = (float*)t_buf(level);
    float* nchw = (level == 1) ? g_s1 : ((level == 2) ? g_s2 : nullptr);

    int pl = tid & 31, cl = tid >> 5;
#pragma unroll
    for (int j = 0; j < 4; ++j) {
        int c = c0 + cl + 8*j;
        int p = p0 + pl;
        float v = __ldg(xin + ((size_t)(b*256 + c))*HW + p);
        if (tprev) {
            int y = p / Wc, x = p % Wc;
            v += __ldg(tprev + ((size_t)(b*256 + c))*(HW >> 2) + (y >> 1)*(Wc >> 1) + (x >> 1));
        }
        tile[cl + 8*j][pl] = v;
        if (nchw) nchw[((size_t)(b*256 + c))*HW + p] = v;
    }
    __syncthreads();
    int cl2 = tid & 31, pl2 = tid >> 5;
#pragma unroll
    for (int j = 0; j < 4; ++j) {
        int p = p0 + pl2 + 8*j;
        nhwc[((size_t)(b*HW + p))*256 + c0 + cl2] = tile[cl2][pl2 + 8*j];
    }
}

// ---------------- offset conv (NCHW input), C split 8 ways -> partials ----------------
__global__ void k_offconv(const float* __restrict__ s_ext, int level, int Hc, int Wc) {
    int hw = Hc * Wc;
    int i = blockIdx.x * blockDim.x + threadIdx.x;
    if (i >= 8 * hw) return;
    int cs = blockIdx.y;
    int b = i / hw, p = i % hw;
    int y = p / Wc, x = p % Wc;
    const float* s = s_nchw(s_ext, level);

    float2 acc[9];
#pragma unroll
    for (int o = 0; o < 9; ++o) acc[o] = make_float2(0.f, 0.f);

    const float*  sb = s + ((size_t)b*256 + (size_t)cs*32) * hw;
    const float2* wb = (const float2*)(g_owt + (size_t)level*2304*18 + (size_t)cs*32*9*18);

    for (int c = 0; c < 32; ++c) {
        float sv[9];
#pragma unroll
        for (int k = 0; k < 9; ++k) {
            int yy = y + k/3 - 1, xx = x + (k%3) - 1;
            sv[k] = (yy >= 0 && yy < Hc && xx >= 0 && xx < Wc)
                        ? __ldg(sb + (size_t)c*hw + yy*Wc + xx) : 0.f;
        }
        const float2* wr = wb + c * 81;
#pragma unroll
        for (int k = 0; k < 9; ++k) {
            float v = sv[k];
#pragma unroll
            for (int o = 0; o < 9; ++o) {
                float2 w = __ldg(&wr[k*9 + o]);
                acc[o].x += v * w.x;
                acc[o].y += v * w.y;
            }
        }
    }
    size_t base = (size_t)cs * (size_t)(8*18*hw);
#pragma unroll
    for (int o = 0; o < 9; ++o) {
        g_offp[base + ((size_t)(b*18 + 2*o    ))*hw + p] = acc[o].x;
        g_offp[base + ((size_t)(b*18 + 2*o + 1))*hw + p] = acc[o].y;
    }
}

// ---------------- deterministic K-split reduce: out = bias + sum_s part[s] ----------------
__global__ void k_reduce(const float* __restrict__ bias, float* __restrict__ outp,
                         int hw, int S) {
    int n4 = (8*256*hw) >> 2;
    int i = blockIdx.x * blockDim.x + threadIdx.x;
    if (i >= n4) return;
    const float4* p4 = (const float4*)g_part;
    float4 a = p4[i];
    for (int s = 1; s < S; ++s) {
        float4 q = p4[(size_t)s * n4 + i];
        a.x += q.x; a.y += q.y; a.z += q.z; a.w += q.w;
    }
    int oc = ((i << 2) / hw) & 255;
    float bv = __ldg(bias + oc);
    a.x += bv; a.y += bv; a.z += bv; a.w += bv;
    ((float4*)outp)[i] = a;
}

// ---------------- main conv: mma.sync fp16 single-pass W, dual staged gather ----------------
#define WSTRIDE 20480
#define VOFF    40960
#define VSTRIDE 5120
#define COFF    51200
#define CWOFF   60416
#define DSMEM_BYTES 69632

__device__ __forceinline__ void prefetch_w(
    uint32_t sbase, const __half* gw, int tid, int chn)
{
    const char* ph = (const char*)(gw + (size_t)tid * 2304 + chn * 32);
    uint32_t dh = sbase + (chn & 1) * WSTRIDE + tid * 80;
#pragma unroll
    for (int u = 0; u < 4; ++u) cp16(dh + u*16, ph + u*16);
}

// staged gather: load phase (LDGs only, results held in regs) + store phase (after mma)
struct GStage {
    float4 v0, v1, v2, v3;
    float4 w;
    int px;
};

__device__ __forceinline__ void gather_load(
    const char* dsm, const float* __restrict__ sb, int tid, int chn, int iter, GStage& s)
{
    const int4*   sIdx = (const int4*)(dsm + COFF);
    const float4* sWgt = (const float4*)(dsm + CWOFF);
    int kn = chn >> 3;
    const float* bp = sb + ((chn & 7) << 5) + ((tid & 7) << 2);
    s.px = (tid >> 3) + 32 * iter;
    int4 id = sIdx[kn*64 + s.px];
    s.w = sWgt[kn*64 + s.px];
    s.v0 = make_float4(0.f, 0.f, 0.f, 0.f);
    s.v1 = s.v0; s.v2 = s.v0; s.v3 = s.v0;
    if (s.w.x != 0.f) s.v0 = __ldg((const float4*)(bp + id.x));
    if (s.w.y != 0.f) s.v1 = __ldg((const float4*)(bp + id.y));
    if (s.w.z != 0.f) s.v2 = __ldg((const float4*)(bp + id.z));
    if (s.w.w != 0.f) s.v3 = __ldg((const float4*)(bp + id.w));
}

__device__ __forceinline__ void gather_store(
    char* dsm, int tid, int chn, const GStage& s)
{
    char* Vb = dsm + VOFF + (chn & 1) * VSTRIDE;
    float4 a;
    a.x = s.w.x*s.v0.x + s.w.y*s.v1.x + s.w.z*s.v2.x + s.w.w*s.v3.x;
    a.y = s.w.x*s.v0.y + s.w.y*s.v1.y + s.w.z*s.v2.y + s.w.w*s.v3.y;
    a.z = s.w.x*s.v0.z + s.w.y*s.v1.z + s.w.z*s.v2.z + s.w.w*s.v3.z;
    a.w = s.w.x*s.v0.w + s.w.y*s.v1.w + s.w.z*s.v2.w + s.w.w*s.v3.w;
    __half2 h01 = __floats2half2_rn(a.x, a.y);
    __half2 h23 = __floats2half2_rn(a.z, a.w);
    *(uint2*)(Vb + s.px * 80 + (tid & 7) * 8) =
        make_uint2(*(uint32_t*)&h01, *(uint32_t*)&h23);
}

__global__ __launch_bounds__(256, 2) void k_dconv_mma(
    int level, int has_off, const float* __restrict__ off_b_lvl,
    const float* __restrict__ bias, float* __restrict__ outp, int HW, int Wc,
    int nch, int use_part)
{
    extern __shared__ char dsm[];
    uint32_t sbase = smem_u32(dsm);

    int tid = threadIdx.x;
    int lane = tid & 31, wid = tid >> 5;
    int b  = blockIdx.y;
    int p0 = blockIdx.x * 64;
    int ks0 = blockIdx.z * nch;
    int warpM = wid & 3, warpN = wid >> 2;
    int ocbase = warpM * 64, nbase = warpN * 32;
    int g = lane >> 2, t = lane & 3;

    const float* sb = t_buf(level) + (size_t)b * HW * 256 + (size_t)p0 * 256;
    const __half* gw = g_w + (size_t)level * 256 * 2304;

    prefetch_w(sbase, gw, tid, ks0);
    asm volatile("cp.async.commit_group;" ::: "memory");

    // ---- fused coefficient prologue (offreduce + bilinear coef) ----
    int4*   sIdx = (int4*)(dsm + COFF);
    float4* sWgt = (float4*)(dsm + CWOFF);
    float fH = (float)((HW / Wc) - 1), fW = (float)(Wc - 1);
    for (int i = tid; i < 576; i += 256) {
        int k = i >> 6, px = i & 63;
        int p = p0 + px;
        int y = p / Wc, x = p % Wc;
        float dy = 0.f, dx = 0.f;
        if (has_off) {
            dy = __ldg(off_b_lvl + 2*k);
            dx = __ldg(off_b_lvl + 2*k + 1);
            size_t basei  = ((size_t)(b*18 + 2*k))*HW + p;
            size_t stride = (size_t)8*18*HW;
#pragma unroll
            for (int cs = 0; cs < 8; ++cs) {
                dy += g_offp[(size_t)cs*stride + basei];
                dx += g_offp[(size_t)cs*stride + basei + HW];
            }
        }
        float py = (float)(y + k/3 - 1) + dy;
        float px_f = (float)(x + (k%3) - 1) + dx;
        float y0 = floorf(py), x0 = floorf(px_f);
        float ly = py - y0, lx = px_f - x0;
        int id[4]; float wv[4];
#pragma unroll
        for (int q = 0; q < 4; ++q) {
            float yf = y0 + (float)(q >> 1);
            float xf = x0 + (float)(q & 1);
            float wy = (q >> 1) ? ly : 1.f - ly;
            float wx = (q & 1)  ? lx : 1.f - lx;
            bool v = (yf >= 0.f) && (yf <= fH) && (xf >= 0.f) && (xf <= fW);
            float yc = fminf(fmaxf(yf, 0.f), fH);
            float xc = fminf(fmaxf(xf, 0.f), fW);
            id[q] = (((int)yc * Wc + (int)xc) - p0) * 256;   // relative to sb
            wv[q] = v ? wy * wx : 0.f;
        }
        sIdx[i] = make_int4(id[0], id[1], id[2], id[3]);
        sWgt[i] = make_float4(wv[0], wv[1], wv[2], wv[3]);
    }
    __syncthreads();

    // prologue gather for first chunk
    {
        GStage s0, s1;
        gather_load((const char*)dsm, sb, tid, ks0, 0, s0);
        gather_load((const char*)dsm, sb, tid, ks0, 1, s1);
        gather_store(dsm, tid, ks0, s0);
        gather_store(dsm, tid, ks0, s1);
    }
    asm volatile("cp.async.wait_group 0;" ::: "memory");
    __syncthreads();

    float acc[4][4][4];
#pragma unroll
    for (int mt = 0; mt < 4; ++mt)
#pragma unroll
        for (int nt = 0; nt < 4; ++nt)
#pragma unroll
            for (int q = 0; q < 4; ++q) acc[mt][nt][q] = 0.f;

    int laneoff = (lane & 15) * 80 + (lane >> 4) * 16;
    int kend = ks0 + nch;

    for (int ch = ks0; ch < kend; ++ch) {
        uint32_t wb = sbase + (ch & 1) * WSTRIDE;
        uint32_t vb = sbase + VOFF + (ch & 1) * VSTRIDE;
        bool pre = (ch + 1 < kend);

        if (pre) prefetch_w(sbase, gw, tid, ch + 1);
        asm volatile("cp.async.commit_group;" ::: "memory");

        GStage s0, s1;
        if (pre) {
            gather_load((const char*)dsm, sb, tid, ch + 1, 0, s0);
            gather_load((const char*)dsm, sb, tid, ch + 1, 1, s1);
        }

        // ---- mma ks=0 (covers s0's LDG latency) ----
        {
            int kb = 0;
            uint32_t B[4][2];
            {
                uint32_t t0, t1, t2, t3;
                ldsm4(vb + (uint32_t)nbase*80 + laneoff + kb, t0, t1, t2, t3);
                B[0][0] = t0; B[1][0] = t1; B[0][1] = t2; B[1][1] = t3;
                ldsm4(vb + (uint32_t)(nbase + 16)*80 + laneoff + kb, t0, t1, t2, t3);
                B[2][0] = t0; B[3][0] = t1; B[2][1] = t2; B[3][1] = t3;
            }
#pragma unroll
            for (int mt = 0; mt < 4; ++mt) {
                uint32_t A[4];
                ldsm4(wb + (uint32_t)(ocbase + mt*16)*80 + laneoff + kb,
                      A[0], A[1], A[2], A[3]);
#pragma unroll
                for (int nt = 0; nt < 4; ++nt)
                    mma_fp16(acc[mt][nt], A, B[nt]);
            }
        }

        if (pre) gather_store(dsm, tid, ch + 1, s0);

        // ---- mma ks=1 (covers s1's LDG latency) ----
        {
            int kb = 32;
            uint32_t B[4][2];
            {
                uint32_t t0, t1, t2, t3;
                ldsm4(vb + (uint32_t)nbase*80 + laneoff + kb, t0, t1, t2, t3);
                B[0][0] = t0; B[1][0] = t1; B[0][1] = t2; B[1][1] = t3;
                ldsm4(vb + (uint32_t)(nbase + 16)*80 + laneoff + kb, t0, t1, t2, t3);
                B[2][0] = t0; B[3][0] = t1; B[2][1] = t2; B[3][1] = t3;
            }
#pragma unroll
            for (int mt = 0; mt < 4; ++mt) {
                uint32_t A[4];
                ldsm4(wb + (uint32_t)(ocbase + mt*16)*80 + laneoff + kb,
                      A[0], A[1], A[2], A[3]);
#pragma unroll
                for (int nt = 0; nt < 4; ++nt)
                    mma_fp16(acc[mt][nt], A, B[nt]);
            }
        }

        if (pre) gather_store(dsm, tid, ch + 1, s1);

        asm volatile("cp.async.wait_group 0;" ::: "memory");
        __syncthreads();
    }

    // ---- epilogue ----
    if (use_part) {
        float* pp = g_part + (size_t)blockIdx.z * 8 * 256 * HW;
#pragma unroll
        for (int mt = 0; mt < 4; ++mt) {
            int oc = ocbase + mt*16 + g;
            float* r0 = pp + ((size_t)(b*256 + oc    ))*HW + p0 + nbase + 2*t;
            float* r1 = pp + ((size_t)(b*256 + oc + 8))*HW + p0 + nbase + 2*t;
#pragma unroll
            for (int nt = 0; nt < 4; ++nt) {
                *(float2*)(r0 + nt*8) = make_float2(acc[mt][nt][0], acc[mt][nt][1]);
                *(float2*)(r1 + nt*8) = make_float2(acc[mt][nt][2], acc[mt][nt][3]);
            }
        }
    } else {
#pragma unroll
        for (int mt = 0; mt < 4; ++mt) {
            int oc = ocbase + mt*16 + g;
            float b0 = __ldg(bias + oc);
            float b1 = __ldg(bias + oc + 8);
            float* r0 = outp + ((size_t)(b*256 + oc    ))*HW + p0 + nbase + 2*t;
            float* r1 = outp + ((size_t)(b*256 + oc + 8))*HW + p0 + nbase + 2*t;
#pragma unroll
            for (int nt = 0; nt < 4; ++nt) {
                float2 u0 = make_float2(acc[mt][nt][0] + b0, acc[mt][nt][1] + b0);
                float2 u1 = make_float2(acc[mt][nt][2] + b1, acc[mt][nt][3] + b1);
                *(float2*)(r0 + nt*8) = u0;
                *(float2*)(r1 + nt*8) = u1;
            }
        }
    }
}

// ---------------- host side ----------------
static inline int divup(int a, int b) { return (a + b - 1) / b; }

extern "C" void kernel_launch(void* const* d_in, const int* in_sizes, int n_in,
                              void* d_out, int out_size) {
    const float* x0      = (const float*)d_in[0];
    const float* x1      = (const float*)d_in[1];
    const float* x2      = (const float*)d_in[2];
    const float* x3      = (const float*)d_in[3];
    const float* weights = (const float*)d_in[4];
    const float* biases  = (const float*)d_in[5];
    const float* off_w   = (const float*)d_in[6];
    const float* off_b   = (const float*)d_in[7];
    float* out = (float*)d_out;

    const size_t T0 = 0;
    const size_t T1 = 33554432;
    const size_t T2 = 41943040;
    const size_t T3 = 44040192;

    (void)in_sizes; (void)n_in; (void)out_size;

    cudaFuncSetAttribute(k_dconv_mma, cudaFuncAttributeMaxDynamicSharedMemorySize, DSMEM_BYTES);

    k_prep<<<divup(4*256*2304, 256), 256>>>(weights, off_w);

    // ---- level 3 (16x16): K-split 8 -> 256 blocks, 9 chunks each ----
    {
        int H = 16, W = 16, hw = 256, S = 8;
        k_fuse_t<<<dim3(hw/32, 8, 8), 256>>>(x3, nullptr, 3, W, hw);
        k_offconv<<<dim3(divup(8*hw, 128), 8), 128>>>(x3, 3, H, W);
        k_dconv_mma<<<dim3(hw/64, 8, S), 256, DSMEM_BYTES>>>(3, 1, off_b + 3*18,
                                                             nullptr, nullptr, hw, W, 72/S, 1);
        k_reduce<<<divup(8*256*hw/4, 256), 256>>>(biases + 3*256, out + T3, hw, S);
    }
    // ---- level 2 (32x32): K-split 4 -> 512 blocks, 18 chunks each ----
    {
        int H = 32, W = 32, hw = 1024, S = 4;
        k_fuse_t<<<dim3(hw/32, 8, 8), 256>>>(x2, out + T3, 2, W, hw);
        k_offconv<<<dim3(divup(8*hw, 128), 8), 128>>>(nullptr, 2, H, W);
        k_dconv_mma<<<dim3(hw/64, 8, S), 256, DSMEM_BYTES>>>(2, 1, off_b + 2*18,
                                                             nullptr, nullptr, hw, W, 72/S, 1);
        k_reduce<<<divup(8*256*hw/4, 256), 256>>>(biases + 2*256, out + T2, hw, S);
    }
    // ---- level 1 (64x64): no split (512 blocks) ----
    {
        int H = 64, W = 64, hw = 4096;
        k_fuse_t<<<dim3(hw/32, 8, 8), 256>>>(x1, out + T2, 1, W, hw);
        k_offconv<<<dim3(divup(8*hw, 128), 8), 128>>>(nullptr, 1, H, W);
        k_dconv_mma<<<dim3(hw/64, 8, 1), 256, DSMEM_BYTES>>>(1, 1, off_b + 1*18,
                                                             biases + 256, out + T1, hw, W, 72, 0);
    }
    // ---- level 0 (128x128): plain conv, no split (2048 blocks) ----
    {
        int H = 128, W = 128, hw = 16384;
        k_fuse_t<<<dim3(hw/32, 8, 8), 256>>>(x0, out + T1, 0, W, hw);
        k_dconv_mma<<<dim3(hw/64, 8, 1), 256, DSMEM_BYTES>>>(0, 0, nullptr,
                                                             biases, out + T0, hw, W, 72, 0);
    }
}

// round 15
// speedup vs baseline: 2.5432x; 1.0664x over previous
#include <cuda_runtime.h>
#include <cuda_fp16.h>
#include <cstdint>

// ---------------- scratch (static device globals; no allocation) ----------------
__device__ __align__(16) __half g_t0h[8*128*128*256]; // NHWC fused input L0 (fp16)
__device__ __align__(16) float g_t1[8*64*64*256];    // NHWC fused input L1
__device__ __align__(16) float g_t2[8*32*32*256];    // NHWC fused input L2
__device__ __align__(16) float g_t3[8*16*16*256];    // NHWC x3 L3
__device__ __align__(16) float g_s1[8*256*64*64];    // NCHW fused L1 (offconv)
__device__ __align__(16) float g_s2[8*256*32*32];    // NCHW fused L2 (offconv)
__device__ float  g_offp[8*8*18*64*64];              // c-split offset-conv partials
__device__ float  g_owt[4*2304*18];
__device__ __align__(16) float g_part[8*8*256*256*4]; // K-split partials
__device__ __align__(16) __half g_w[4*256*2304];     // W fp16, [l][o][k*256+c]

__device__ __forceinline__ const float* t_buf(int l) {
    return (l == 1) ? g_t1 : (l == 2 ? g_t2 : g_t3);
}
__device__ __forceinline__ const float* s_nchw(const float* ext, int l) {
    if (ext) return ext;
    return (l == 1) ? g_s1 : g_s2;
}

__device__ __forceinline__ uint32_t smem_u32(const void* p) {
    uint32_t a;
    asm("{ .reg .u64 t; cvta.to.shared.u64 t, %1; cvt.u32.u64 %0, t; }" : "=r"(a) : "l"(p));
    return a;
}
__device__ __forceinline__ void cp16(uint32_t d, const void* s) {
    asm volatile("cp.async.cg.shared.global [%0], [%1], 16;" :: "r"(d), "l"(s) : "memory");
}
__device__ __forceinline__ void cp16z(uint32_t d, const void* s, int sz) {
    asm volatile("cp.async.cg.shared.global [%0], [%1], 16, %2;"
                 :: "r"(d), "l"(s), "r"(sz) : "memory");
}
__device__ __forceinline__ void mma_fp16(float* c, const uint32_t* a, const uint32_t* b) {
    asm volatile(
        "mma.sync.aligned.m16n8k16.row.col.f32.f16.f16.f32 "
        "{%0,%1,%2,%3}, {%4,%5,%6,%7}, {%8,%9}, {%0,%1,%2,%3};"
        : "+f"(c[0]), "+f"(c[1]), "+f"(c[2]), "+f"(c[3])
        : "r"(a[0]), "r"(a[1]), "r"(a[2]), "r"(a[3]), "r"(b[0]), "r"(b[1]));
}
__device__ __forceinline__ void ldsm4(uint32_t a, uint32_t& r0, uint32_t& r1,
                                      uint32_t& r2, uint32_t& r3) {
    asm volatile("ldmatrix.sync.aligned.m8n8.x4.shared.b16 {%0,%1,%2,%3}, [%4];"
                 : "=r"(r0), "=r"(r1), "=r"(r2), "=r"(r3) : "r"(a));
}

// ---------------- weight prep: fp16 convert, tap-major reorder ----------------
__global__ void k_prep(const float* __restrict__ w, const float* __restrict__ ow) {
    int i = blockIdx.x * blockDim.x + threadIdx.x;
    if (i < 4*256*2304) {
        int ck2 = i % 2304;
        int o   = (i / 2304) & 255;
        int l   = i / (2304*256);
        int k = ck2 >> 8, c = ck2 & 255;
        float v = __ldg(w + ((size_t)((l*256 + o)*256 + c))*9 + k);
        g_w[i] = __float2half_rn(v);
    }
    if (i < 4*2304*18) {
        int o  = i % 18;
        int ck = (i / 18) % 2304;
        int l  = i / (2304*18);
        g_owt[i] = __ldg(ow + ((size_t)(l*18 + o))*2304 + ck);
    }
}

// ---------------- fuse + transpose: NHWC (fp16 for L0, fp32 for L1-3), NCHW copy L1/2 ----------------
__global__ void k_fuse_t(const float* __restrict__ xin, const float* __restrict__ tprev,
                         int level, int Wc, int HW) {
    __shared__ float tile[32][33];
    int tid = threadIdx.x;
    int p0 = blockIdx.x * 32;
    int c0 = blockIdx.y * 32;
    int b  = blockIdx.z;

    float* nchw = (level == 1) ? g_s1 : ((level == 2) ? g_s2 : nullptr);

    int pl = tid & 31, cl = tid >> 5;
#pragma unroll
    for (int j = 0; j < 4; ++j) {
        int c = c0 + cl + 8*j;
        int p = p0 + pl;
        float v = __ldg(xin + ((size_t)(b*256 + c))*HW + p);
        if (tprev) {
            int y = p / Wc, x = p % Wc;
            v += __ldg(tprev + ((size_t)(b*256 + c))*(HW >> 2) + (y >> 1)*(Wc >> 1) + (x >> 1));
        }
        tile[cl + 8*j][pl] = v;
        if (nchw) nchw[((size_t)(b*256 + c))*HW + p] = v;
    }
    __syncthreads();
    int cl2 = tid & 31, pl2 = tid >> 5;
    if (level == 0) {
#pragma unroll
        for (int j = 0; j < 4; ++j) {
            int p = p0 + pl2 + 8*j;
            g_t0h[((size_t)(b*HW + p))*256 + c0 + cl2] =
                __float2half_rn(tile[cl2][pl2 + 8*j]);
        }
    } else {
        float* nhwc = (float*)t_buf(level);
#pragma unroll
        for (int j = 0; j < 4; ++j) {
            int p = p0 + pl2 + 8*j;
            nhwc[((size_t)(b*HW + p))*256 + c0 + cl2] = tile[cl2][pl2 + 8*j];
        }
    }
}

// ---------------- offset conv (NCHW input), C split 8 ways -> partials ----------------
__global__ void k_offconv(const float* __restrict__ s_ext, int level, int Hc, int Wc) {
    int hw = Hc * Wc;
    int i = blockIdx.x * blockDim.x + threadIdx.x;
    if (i >= 8 * hw) return;
    int cs = blockIdx.y;
    int b = i / hw, p = i % hw;
    int y = p / Wc, x = p % Wc;
    const float* s = s_nchw(s_ext, level);

    float2 acc[9];
#pragma unroll
    for (int o = 0; o < 9; ++o) acc[o] = make_float2(0.f, 0.f);

    const float*  sb = s + ((size_t)b*256 + (size_t)cs*32) * hw;
    const float2* wb = (const float2*)(g_owt + (size_t)level*2304*18 + (size_t)cs*32*9*18);

    for (int c = 0; c < 32; ++c) {
        float sv[9];
#pragma unroll
        for (int k = 0; k < 9; ++k) {
            int yy = y + k/3 - 1, xx = x + (k%3) - 1;
            sv[k] = (yy >= 0 && yy < Hc && xx >= 0 && xx < Wc)
                        ? __ldg(sb + (size_t)c*hw + yy*Wc + xx) : 0.f;
        }
        const float2* wr = wb + c * 81;
#pragma unroll
        for (int k = 0; k < 9; ++k) {
            float v = sv[k];
#pragma unroll
            for (int o = 0; o < 9; ++o) {
                float2 w = __ldg(&wr[k*9 + o]);
                acc[o].x += v * w.x;
                acc[o].y += v * w.y;
            }
        }
    }
    size_t base = (size_t)cs * (size_t)(8*18*hw);
#pragma unroll
    for (int o = 0; o < 9; ++o) {
        g_offp[base + ((size_t)(b*18 + 2*o    ))*hw + p] = acc[o].x;
        g_offp[base + ((size_t)(b*18 + 2*o + 1))*hw + p] = acc[o].y;
    }
}

// ---------------- deterministic K-split reduce: out = bias + sum_s part[s] ----------------
__global__ void k_reduce(const float* __restrict__ bias, float* __restrict__ outp,
                         int hw, int S) {
    int n4 = (8*256*hw) >> 2;
    int i = blockIdx.x * blockDim.x + threadIdx.x;
    if (i >= n4) return;
    const float4* p4 = (const float4*)g_part;
    float4 a = p4[i];
    for (int s = 1; s < S; ++s) {
        float4 q = p4[(size_t)s * n4 + i];
        a.x += q.x; a.y += q.y; a.z += q.z; a.w += q.w;
    }
    int oc = ((i << 2) / hw) & 255;
    float bv = __ldg(bias + oc);
    a.x += bv; a.y += bv; a.z += bv; a.w += bv;
    ((float4*)outp)[i] = a;
}

// ================= L0 specialized plain conv: pure cp.async V path =================
// tile 256oc x 64px, K=2304 tap-major, chunk 32. smem: W 2x20480 | V 2x5120 = 51200
#define W0STRIDE 20480
#define V0OFF    40960
#define V0STRIDE 5120
#define DSMEM0   51200

__global__ __launch_bounds__(256, 2) void k_conv0(
    const float* __restrict__ bias, float* __restrict__ outp)
{
    const int HW = 16384, Wc = 128;
    extern __shared__ char dsm[];
    uint32_t sbase = smem_u32(dsm);

    int tid = threadIdx.x;
    int lane = tid & 31, wid = tid >> 5;
    int b  = blockIdx.y;
    int p0 = blockIdx.x * 64;
    int warpM = wid & 3, warpN = wid >> 2;
    int ocbase = warpM * 64, nbase = warpN * 32;
    int g = lane >> 2, t = lane & 3;

    const __half* sbh = g_t0h + (size_t)b * HW * 256;
    const __half* gw  = g_w;     // level 0

    // V-prefetch role: thread -> (pixel row, 16B quarter)
    int vpx = tid >> 2, vq = tid & 3;
    int p  = p0 + vpx;
    int y  = p >> 7, x = p & 127;

    // per-chunk V prefetch: one 16B cp.async (8 fp16 channels) with border zfill
    auto pv = [&](int ch) {
        int kn = ch >> 3;
        int cg = ((ch & 7) << 5) + (vq << 3);
        int ky = kn / 3 - 1, kx = kn - (kn / 3) * 3 - 1;
        int yy = y + ky, xx = x + kx;
        bool valid = ((unsigned)yy < 128u) && ((unsigned)xx < 128u);
        const __half* src = sbh + ((size_t)(valid ? (yy << 7) + xx : 0)) * 256 + cg;
        uint32_t dst = sbase + V0OFF + (ch & 1) * V0STRIDE + vpx * 80 + vq * 16;
        cp16z(dst, src, valid ? 16 : 0);
    };
    auto pw = [&](int ch) {
        const char* ph = (const char*)(gw + (size_t)tid * 2304 + ch * 32);
        uint32_t dh = sbase + (ch & 1) * W0STRIDE + tid * 80;
#pragma unroll
        for (int u = 0; u < 4; ++u) cp16(dh + u*16, ph + u*16);
    };

    pw(0); pv(0);
    asm volatile("cp.async.commit_group;" ::: "memory");
    asm volatile("cp.async.wait_group 0;" ::: "memory");
    __syncthreads();

    float acc[4][4][4];
#pragma unroll
    for (int mt = 0; mt < 4; ++mt)
#pragma unroll
        for (int nt = 0; nt < 4; ++nt)
#pragma unroll
            for (int q = 0; q < 4; ++q) acc[mt][nt][q] = 0.f;

    int laneoff = (lane & 15) * 80 + (lane >> 4) * 16;

    for (int ch = 0; ch < 72; ++ch) {
        uint32_t wb = sbase + (ch & 1) * W0STRIDE;
        uint32_t vb = sbase + V0OFF + (ch & 1) * V0STRIDE;

        if (ch < 71) { pw(ch + 1); pv(ch + 1); }
        asm volatile("cp.async.commit_group;" ::: "memory");

#pragma unroll
        for (int ks = 0; ks < 2; ++ks) {
            int kb = ks * 32;
            uint32_t B[4][2];
            {
                uint32_t t0, t1, t2, t3;
                ldsm4(vb + (uint32_t)nbase*80 + laneoff + kb, t0, t1, t2, t3);
                B[0][0] = t0; B[1][0] = t1; B[0][1] = t2; B[1][1] = t3;
                ldsm4(vb + (uint32_t)(nbase + 16)*80 + laneoff + kb, t0, t1, t2, t3);
                B[2][0] = t0; B[3][0] = t1; B[2][1] = t2; B[3][1] = t3;
            }
#pragma unroll
            for (int mt = 0; mt < 4; ++mt) {
                uint32_t A[4];
                ldsm4(wb + (uint32_t)(ocbase + mt*16)*80 + laneoff + kb,
                      A[0], A[1], A[2], A[3]);
#pragma unroll
                for (int nt = 0; nt < 4; ++nt)
                    mma_fp16(acc[mt][nt], A, B[nt]);
            }
        }
        asm volatile("cp.async.wait_group 0;" ::: "memory");
        __syncthreads();
    }

#pragma unroll
    for (int mt = 0; mt < 4; ++mt) {
        int oc = ocbase + mt*16 + g;
        float b0 = __ldg(bias + oc);
        float b1 = __ldg(bias + oc + 8);
        float* r0 = outp + ((size_t)(b*256 + oc    ))*HW + p0 + nbase + 2*t;
        float* r1 = outp + ((size_t)(b*256 + oc + 8))*HW + p0 + nbase + 2*t;
#pragma unroll
        for (int nt = 0; nt < 4; ++nt) {
            *(float2*)(r0 + nt*8) = make_float2(acc[mt][nt][0] + b0, acc[mt][nt][1] + b0);
            *(float2*)(r1 + nt*8) = make_float2(acc[mt][nt][2] + b1, acc[mt][nt][3] + b1);
        }
    }
}

// ---------------- deform conv (levels 1-3): unchanged from R13 ----------------
#define WSTRIDE 20480
#define VOFF    40960
#define VSTRIDE 5120
#define COFF    51200
#define CWOFF   60416
#define DSMEM_BYTES 69632

__device__ __forceinline__ void prefetch_w(
    uint32_t sbase, const __half* gw, int tid, int chn)
{
    const char* ph = (const char*)(gw + (size_t)tid * 2304 + chn * 32);
    uint32_t dh = sbase + (chn & 1) * WSTRIDE + tid * 80;
#pragma unroll
    for (int u = 0; u < 4; ++u) cp16(dh + u*16, ph + u*16);
}

struct GStage {
    float4 v0, v1, v2, v3;
    float4 w;
    int px;
};

__device__ __forceinline__ void gather_load(
    const char* dsm, const float* __restrict__ sb, int tid, int chn, int iter, GStage& s)
{
    const int4*   sIdx = (const int4*)(dsm + COFF);
    const float4* sWgt = (const float4*)(dsm + CWOFF);
    int kn = chn >> 3;
    const float* bp = sb + ((chn & 7) << 5) + ((tid & 7) << 2);
    s.px = (tid >> 3) + 32 * iter;
    int4 id = sIdx[kn*64 + s.px];
    s.w = sWgt[kn*64 + s.px];
    s.v0 = make_float4(0.f, 0.f, 0.f, 0.f);
    s.v1 = s.v0; s.v2 = s.v0; s.v3 = s.v0;
    if (s.w.x != 0.f) s.v0 = __ldg((const float4*)(bp + id.x));
    if (s.w.y != 0.f) s.v1 = __ldg((const float4*)(bp + id.y));
    if (s.w.z != 0.f) s.v2 = __ldg((const float4*)(bp + id.z));
    if (s.w.w != 0.f) s.v3 = __ldg((const float4*)(bp + id.w));
}

__device__ __forceinline__ void gather_store(
    char* dsm, int tid, int chn, const GStage& s)
{
    char* Vb = dsm + VOFF + (chn & 1) * VSTRIDE;
    float4 a;
    a.x = s.w.x*s.v0.x + s.w.y*s.v1.x + s.w.z*s.v2.x + s.w.w*s.v3.x;
    a.y = s.w.x*s.v0.y + s.w.y*s.v1.y + s.w.z*s.v2.y + s.w.w*s.v3.y;
    a.z = s.w.x*s.v0.z + s.w.y*s.v1.z + s.w.z*s.v2.z + s.w.w*s.v3.z;
    a.w = s.w.x*s.v0.w + s.w.y*s.v1.w + s.w.z*s.v2.w + s.w.w*s.v3.w;
    __half2 h01 = __floats2half2_rn(a.x, a.y);
    __half2 h23 = __floats2half2_rn(a.z, a.w);
    *(uint2*)(Vb + s.px * 80 + (tid & 7) * 8) =
        make_uint2(*(uint32_t*)&h01, *(uint32_t*)&h23);
}

__global__ __launch_bounds__(256, 2) void k_dconv_mma(
    int level, const float* __restrict__ off_b_lvl,
    const float* __restrict__ bias, float* __restrict__ outp, int HW, int Wc,
    int nch, int use_part)
{
    extern __shared__ char dsm[];
    uint32_t sbase = smem_u32(dsm);

    int tid = threadIdx.x;
    int lane = tid & 31, wid = tid >> 5;
    int b  = blockIdx.y;
    int p0 = blockIdx.x * 64;
    int ks0 = blockIdx.z * nch;
    int warpM = wid & 3, warpN = wid >> 2;
    int ocbase = warpM * 64, nbase = warpN * 32;
    int g = lane >> 2, t = lane & 3;

    const float* sb = t_buf(level) + (size_t)b * HW * 256 + (size_t)p0 * 256;
    const __half* gw = g_w + (size_t)level * 256 * 2304;

    prefetch_w(sbase, gw, tid, ks0);
    asm volatile("cp.async.commit_group;" ::: "memory");

    // ---- fused coefficient prologue (offreduce + bilinear coef) ----
    int4*   sIdx = (int4*)(dsm + COFF);
    float4* sWgt = (float4*)(dsm + CWOFF);
    float fH = (float)((HW / Wc) - 1), fW = (float)(Wc - 1);
    for (int i = tid; i < 576; i += 256) {
        int k = i >> 6, px = i & 63;
        int p = p0 + px;
        int y = p / Wc, x = p % Wc;
        float dy = __ldg(off_b_lvl + 2*k);
        float dx = __ldg(off_b_lvl + 2*k + 1);
        size_t basei  = ((size_t)(b*18 + 2*k))*HW + p;
        size_t stride = (size_t)8*18*HW;
#pragma unroll
        for (int cs = 0; cs < 8; ++cs) {
            dy += g_offp[(size_t)cs*stride + basei];
            dx += g_offp[(size_t)cs*stride + basei + HW];
        }
        float py = (float)(y + k/3 - 1) + dy;
        float px_f = (float)(x + (k%3) - 1) + dx;
        float y0 = floorf(py), x0 = floorf(px_f);
        float ly = py - y0, lx = px_f - x0;
        int id[4]; float wv[4];
#pragma unroll
        for (int q = 0; q < 4; ++q) {
            float yf = y0 + (float)(q >> 1);
            float xf = x0 + (float)(q & 1);
            float wy = (q >> 1) ? ly : 1.f - ly;
            float wx = (q & 1)  ? lx : 1.f - lx;
            bool v = (yf >= 0.f) && (yf <= fH) && (xf >= 0.f) && (xf <= fW);
            float yc = fminf(fmaxf(yf, 0.f), fH);
            float xc = fminf(fmaxf(xf, 0.f), fW);
            id[q] = (((int)yc * Wc + (int)xc) - p0) * 256;   // relative to sb
            wv[q] = v ? wy * wx : 0.f;
        }
        sIdx[i] = make_int4(id[0], id[1], id[2], id[3]);
        sWgt[i] = make_float4(wv[0], wv[1], wv[2], wv[3]);
    }
    __syncthreads();

    {
        GStage s0, s1;
        gather_load((const char*)dsm, sb, tid, ks0, 0, s0);
        gather_load((const char*)dsm, sb, tid, ks0, 1, s1);
        gather_store(dsm, tid, ks0, s0);
        gather_store(dsm, tid, ks0, s1);
    }
    asm volatile("cp.async.wait_group 0;" ::: "memory");
    __syncthreads();

    float acc[4][4][4];
#pragma unroll
    for (int mt = 0; mt < 4; ++mt)
#pragma unroll
        for (int nt = 0; nt < 4; ++nt)
#pragma unroll
            for (int q = 0; q < 4; ++q) acc[mt][nt][q] = 0.f;

    int laneoff = (lane & 15) * 80 + (lane >> 4) * 16;
    int kend = ks0 + nch;

    for (int ch = ks0; ch < kend; ++ch) {
        uint32_t wb = sbase + (ch & 1) * WSTRIDE;
        uint32_t vb = sbase + VOFF + (ch & 1) * VSTRIDE;
        bool pre = (ch + 1 < kend);

        if (pre) prefetch_w(sbase, gw, tid, ch + 1);
        asm volatile("cp.async.commit_group;" ::: "memory");

        GStage s0, s1;
        if (pre) {
            gather_load((const char*)dsm, sb, tid, ch + 1, 0, s0);
            gather_load((const char*)dsm, sb, tid, ch + 1, 1, s1);
        }

        {
            int kb = 0;
            uint32_t B[4][2];
            {
                uint32_t t0, t1, t2, t3;
                ldsm4(vb + (uint32_t)nbase*80 + laneoff + kb, t0, t1, t2, t3);
                B[0][0] = t0; B[1][0] = t1; B[0][1] = t2; B[1][1] = t3;
                ldsm4(vb + (uint32_t)(nbase + 16)*80 + laneoff + kb, t0, t1, t2, t3);
                B[2][0] = t0; B[3][0] = t1; B[2][1] = t2; B[3][1] = t3;
            }
#pragma unroll
            for (int mt = 0; mt < 4; ++mt) {
                uint32_t A[4];
                ldsm4(wb + (uint32_t)(ocbase + mt*16)*80 + laneoff + kb,
                      A[0], A[1], A[2], A[3]);
#pragma unroll
                for (int nt = 0; nt < 4; ++nt)
                    mma_fp16(acc[mt][nt], A, B[nt]);
            }
        }

        if (pre) gather_store(dsm, tid, ch + 1, s0);

        {
            int kb = 32;
            uint32_t B[4][2];
            {
                uint32_t t0, t1, t2, t3;
                ldsm4(vb + (uint32_t)nbase*80 + laneoff + kb, t0, t1, t2, t3);
                B[0][0] = t0; B[1][0] = t1; B[0][1] = t2; B[1][1] = t3;
                ldsm4(vb + (uint32_t)(nbase + 16)*80 + laneoff + kb, t0, t1, t2, t3);
                B[2][0] = t0; B[3][0] = t1; B[2][1] = t2; B[3][1] = t3;
            }
#pragma unroll
            for (int mt = 0; mt < 4; ++mt) {
                uint32_t A[4];
                ldsm4(wb + (uint32_t)(ocbase + mt*16)*80 + laneoff + kb,
                      A[0], A[1], A[2], A[3]);
#pragma unroll
                for (int nt = 0; nt < 4; ++nt)
                    mma_fp16(acc[mt][nt], A, B[nt]);
            }
        }

        if (pre) gather_store(dsm, tid, ch + 1, s1);

        asm volatile("cp.async.wait_group 0;" ::: "memory");
        __syncthreads();
    }

    if (use_part) {
        float* pp = g_part + (size_t)blockIdx.z * 8 * 256 * HW;
#pragma unroll
        for (int mt = 0; mt < 4; ++mt) {
            int oc = ocbase + mt*16 + g;
            float* r0 = pp + ((size_t)(b*256 + oc    ))*HW + p0 + nbase + 2*t;
            float* r1 = pp + ((size_t)(b*256 + oc + 8))*HW + p0 + nbase + 2*t;
#pragma unroll
            for (int nt = 0; nt < 4; ++nt) {
                *(float2*)(r0 + nt*8) = make_float2(acc[mt][nt][0], acc[mt][nt][1]);
                *(float2*)(r1 + nt*8) = make_float2(acc[mt][nt][2], acc[mt][nt][3]);
            }
        }
    } else {
#pragma unroll
        for (int mt = 0; mt < 4; ++mt) {
            int oc = ocbase + mt*16 + g;
            float b0 = __ldg(bias + oc);
            float b1 = __ldg(bias + oc + 8);
            float* r0 = outp + ((size_t)(b*256 + oc    ))*HW + p0 + nbase + 2*t;
            float* r1 = outp + ((size_t)(b*256 + oc + 8))*HW + p0 + nbase + 2*t;
#pragma unroll
            for (int nt = 0; nt < 4; ++nt) {
                *(float2*)(r0 + nt*8) = make_float2(acc[mt][nt][0] + b0, acc[mt][nt][1] + b0);
                *(float2*)(r1 + nt*8) = make_float2(acc[mt][nt][2] + b1, acc[mt][nt][3] + b1);
            }
        }
    }
}

// ---------------- host side ----------------
static inline int divup(int a, int b) { return (a + b - 1) / b; }

extern "C" void kernel_launch(void* const* d_in, const int* in_sizes, int n_in,
                              void* d_out, int out_size) {
    const float* x0      = (const float*)d_in[0];
    const float* x1      = (const float*)d_in[1];
    const float* x2      = (const float*)d_in[2];
    const float* x3      = (const float*)d_in[3];
    const float* weights = (const float*)d_in[4];
    const float* biases  = (const float*)d_in[5];
    const float* off_w   = (const float*)d_in[6];
    const float* off_b   = (const float*)d_in[7];
    float* out = (float*)d_out;

    const size_t T0 = 0;
    const size_t T1 = 33554432;
    const size_t T2 = 41943040;
    const size_t T3 = 44040192;

    (void)in_sizes; (void)n_in; (void)out_size;

    cudaFuncSetAttribute(k_dconv_mma, cudaFuncAttributeMaxDynamicSharedMemorySize, DSMEM_BYTES);
    cudaFuncSetAttribute(k_conv0, cudaFuncAttributeMaxDynamicSharedMemorySize, DSMEM0);

    k_prep<<<divup(4*256*2304, 256), 256>>>(weights, off_w);

    // ---- level 3 (16x16): K-split 8 ----
    {
        int H = 16, W = 16, hw = 256, S = 8;
        k_fuse_t<<<dim3(hw/32, 8, 8), 256>>>(x3, nullptr, 3, W, hw);
        k_offconv<<<dim3(divup(8*hw, 128), 8), 128>>>(x3, 3, H, W);
        k_dconv_mma<<<dim3(hw/64, 8, S), 256, DSMEM_BYTES>>>(3, off_b + 3*18,
                                                             nullptr, nullptr, hw, W, 72/S, 1);
        k_reduce<<<divup(8*256*hw/4, 256), 256>>>(biases + 3*256, out + T3, hw, S);
    }
    // ---- level 2 (32x32): K-split 4 ----
    {
        int H = 32, W = 32, hw = 1024, S = 4;
        k_fuse_t<<<dim3(hw/32, 8, 8), 256>>>(x2, out + T3, 2, W, hw);
        k_offconv<<<dim3(divup(8*hw, 128), 8), 128>>>(nullptr, 2, H, W);
        k_dconv_mma<<<dim3(hw/64, 8, S), 256, DSMEM_BYTES>>>(2, off_b + 2*18,
                                                             nullptr, nullptr, hw, W, 72/S, 1);
        k_reduce<<<divup(8*256*hw/4, 256), 256>>>(biases + 2*256, out + T2, hw, S);
    }
    // ---- level 1 (64x64): no split ----
    {
        int H = 64, W = 64, hw = 4096;
        k_fuse_t<<<dim3(hw/32, 8, 8), 256>>>(x1, out + T2, 1, W, hw);
        k_offconv<<<dim3(divup(8*hw, 128), 8), 128>>>(nullptr, 1, H, W);
        k_dconv_mma<<<dim3(hw/64, 8, 1), 256, DSMEM_BYTES>>>(1, off_b + 1*18,
                                                             biases + 256, out + T1, hw, W, 72, 0);
    }
    // ---- level 0 (128x128): specialized plain conv, pure cp.async V ----
    {
        int hw = 16384;
        k_fuse_t<<<dim3(hw/32, 8, 8), 256>>>(x0, out + T1, 0, 128, hw);
        k_conv0<<<dim3(hw/64, 8), 256, DSMEM0>>>(biases, out + T0);
    }
}

// round 16
// speedup vs baseline: 2.9251x; 1.1502x over previous
#include <cuda_runtime.h>
#include <cuda_fp16.h>
#include <cstdint>

// ---------------- scratch (static device globals; no allocation) ----------------
__device__ __align__(16) __half g_t0h[8*128*128*256]; // NHWC fused input L0 (fp16)
__device__ __align__(16) float g_t1[8*64*64*256];    // NHWC fused input L1
__device__ __align__(16) float g_t2[8*32*32*256];    // NHWC fused input L2
__device__ __align__(16) float g_t3[8*16*16*256];    // NHWC x3 L3
__device__ __align__(16) float g_s1[8*256*64*64];    // NCHW fused L1 (offconv)
__device__ __align__(16) float g_s2[8*256*32*32];    // NCHW fused L2 (offconv)
__device__ float  g_offp[8*8*18*64*64];              // c-split offset-conv partials
__device__ float  g_owt[4*2304*18];
__device__ __align__(16) float g_part[8*8*256*256*4]; // K-split partials
__device__ __align__(16) __half g_w[4*256*2304];     // W fp16, [l][o][k*256+c]

__device__ __forceinline__ const float* t_buf(int l) {
    return (l == 1) ? g_t1 : (l == 2 ? g_t2 : g_t3);
}
__device__ __forceinline__ const float* s_nchw(const float* ext, int l) {
    if (ext) return ext;
    return (l == 1) ? g_s1 : g_s2;
}

__device__ __forceinline__ uint32_t smem_u32(const void* p) {
    uint32_t a;
    asm("{ .reg .u64 t; cvta.to.shared.u64 t, %1; cvt.u32.u64 %0, t; }" : "=r"(a) : "l"(p));
    return a;
}
__device__ __forceinline__ void cp16(uint32_t d, const void* s) {
    asm volatile("cp.async.cg.shared.global [%0], [%1], 16;" :: "r"(d), "l"(s) : "memory");
}
__device__ __forceinline__ void cp16z(uint32_t d, const void* s, int sz) {
    asm volatile("cp.async.cg.shared.global [%0], [%1], 16, %2;"
                 :: "r"(d), "l"(s), "r"(sz) : "memory");
}
__device__ __forceinline__ void mma_fp16(float* c, const uint32_t* a, const uint32_t* b) {
    asm volatile(
        "mma.sync.aligned.m16n8k16.row.col.f32.f16.f16.f32 "
        "{%0,%1,%2,%3}, {%4,%5,%6,%7}, {%8,%9}, {%0,%1,%2,%3};"
        : "+f"(c[0]), "+f"(c[1]), "+f"(c[2]), "+f"(c[3])
        : "r"(a[0]), "r"(a[1]), "r"(a[2]), "r"(a[3]), "r"(b[0]), "r"(b[1]));
}
__device__ __forceinline__ void ldsm4(uint32_t a, uint32_t& r0, uint32_t& r1,
                                      uint32_t& r2, uint32_t& r3) {
    asm volatile("ldmatrix.sync.aligned.m8n8.x4.shared.b16 {%0,%1,%2,%3}, [%4];"
                 : "=r"(r0), "=r"(r1), "=r"(r2), "=r"(r3) : "r"(a));
}

// ---------------- weight prep: fp16 convert, tap-major reorder ----------------
__global__ void k_prep(const float* __restrict__ w, const float* __restrict__ ow) {
    int i = blockIdx.x * blockDim.x + threadIdx.x;
    if (i < 4*256*2304) {
        int ck2 = i % 2304;
        int o   = (i / 2304) & 255;
        int l   = i / (2304*256);
        int k = ck2 >> 8, c = ck2 & 255;
        float v = __ldg(w + ((size_t)((l*256 + o)*256 + c))*9 + k);
        g_w[i] = __float2half_rn(v);
    }
    if (i < 4*2304*18) {
        int o  = i % 18;
        int ck = (i / 18) % 2304;
        int l  = i / (2304*18);
        g_owt[i] = __ldg(ow + ((size_t)(l*18 + o))*2304 + ck);
    }
}

// ---------------- fuse + transpose: NHWC (fp16 for L0, fp32 for L1-3), NCHW copy L1/2 ----------------
__global__ void k_fuse_t(const float* __restrict__ xin, const float* __restrict__ tprev,
                         int level, int Wc, int HW) {
    __shared__ float tile[32][33];
    int tid = threadIdx.x;
    int p0 = blockIdx.x * 32;
    int c0 = blockIdx.y * 32;
    int b  = blockIdx.z;

    float* nchw = (level == 1) ? g_s1 : ((level == 2) ? g_s2 : nullptr);

    int pl = tid & 31, cl = tid >> 5;
#pragma unroll
    for (int j = 0; j < 4; ++j) {
        int c = c0 + cl + 8*j;
        int p = p0 + pl;
        float v = __ldg(xin + ((size_t)(b*256 + c))*HW + p);
        if (tprev) {
            int y = p / Wc, x = p % Wc;
            v += __ldg(tprev + ((size_t)(b*256 + c))*(HW >> 2) + (y >> 1)*(Wc >> 1) + (x >> 1));
        }
        tile[cl + 8*j][pl] = v;
        if (nchw) nchw[((size_t)(b*256 + c))*HW + p] = v;
    }
    __syncthreads();
    int cl2 = tid & 31, pl2 = tid >> 5;
    if (level == 0) {
#pragma unroll
        for (int j = 0; j < 4; ++j) {
            int p = p0 + pl2 + 8*j;
            g_t0h[((size_t)(b*HW + p))*256 + c0 + cl2] =
                __float2half_rn(tile[cl2][pl2 + 8*j]);
        }
    } else {
        float* nhwc = (float*)t_buf(level);
#pragma unroll
        for (int j = 0; j < 4; ++j) {
            int p = p0 + pl2 + 8*j;
            nhwc[((size_t)(b*HW + p))*256 + c0 + cl2] = tile[cl2][pl2 + 8*j];
        }
    }
}

// ---------------- offset conv (NCHW input), C split 8 ways -> partials ----------------
__global__ void k_offconv(const float* __restrict__ s_ext, int level, int Hc, int Wc) {
    int hw = Hc * Wc;
    int i = blockIdx.x * blockDim.x + threadIdx.x;
    if (i >= 8 * hw) return;
    int cs = blockIdx.y;
    int b = i / hw, p = i % hw;
    int y = p / Wc, x = p % Wc;
    const float* s = s_nchw(s_ext, level);

    float2 acc[9];
#pragma unroll
    for (int o = 0; o < 9; ++o) acc[o] = make_float2(0.f, 0.f);

    const float*  sb = s + ((size_t)b*256 + (size_t)cs*32) * hw;
    const float2* wb = (const float2*)(g_owt + (size_t)level*2304*18 + (size_t)cs*32*9*18);

    for (int c = 0; c < 32; ++c) {
        float sv[9];
#pragma unroll
        for (int k = 0; k < 9; ++k) {
            int yy = y + k/3 - 1, xx = x + (k%3) - 1;
            sv[k] = (yy >= 0 && yy < Hc && xx >= 0 && xx < Wc)
                        ? __ldg(sb + (size_t)c*hw + yy*Wc + xx) : 0.f;
        }
        const float2* wr = wb + c * 81;
#pragma unroll
        for (int k = 0; k < 9; ++k) {
            float v = sv[k];
#pragma unroll
            for (int o = 0; o < 9; ++o) {
                float2 w = __ldg(&wr[k*9 + o]);
                acc[o].x += v * w.x;
                acc[o].y += v * w.y;
            }
        }
    }
    size_t base = (size_t)cs * (size_t)(8*18*hw);
#pragma unroll
    for (int o = 0; o < 9; ++o) {
        g_offp[base + ((size_t)(b*18 + 2*o    ))*hw + p] = acc[o].x;
        g_offp[base + ((size_t)(b*18 + 2*o + 1))*hw + p] = acc[o].y;
    }
}

// ---------------- deterministic K-split reduce: out = bias + sum_s part[s] ----------------
__global__ void k_reduce(const float* __restrict__ bias, float* __restrict__ outp,
                         int hw, int S) {
    int n4 = (8*256*hw) >> 2;
    int i = blockIdx.x * blockDim.x + threadIdx.x;
    if (i >= n4) return;
    const float4* p4 = (const float4*)g_part;
    float4 a = p4[i];
    for (int s = 1; s < S; ++s) {
        float4 q = p4[(size_t)s * n4 + i];
        a.x += q.x; a.y += q.y; a.z += q.z; a.w += q.w;
    }
    int oc = ((i << 2) / hw) & 255;
    float bv = __ldg(bias + oc);
    a.x += bv; a.y += bv; a.z += bv; a.w += bv;
    ((float4*)outp)[i] = a;
}

// ================= L0 plain conv: 128oc x 64px tile, 4-buffer distance-2 pipeline =================
// smem: W 4 x 10240 | V 4 x 5120 = 61440; 3 blocks/SM (24 warps)
#define W0TILE  10240
#define V0OFF2  40960
#define V0TILE  5120
#define DSMEM0  61440

__global__ __launch_bounds__(256, 3) void k_conv0(
    const float* __restrict__ bias, float* __restrict__ outp)
{
    const int HW = 16384;
    extern __shared__ char dsm[];
    uint32_t sbase = smem_u32(dsm);

    int tid = threadIdx.x;
    int lane = tid & 31, wid = tid >> 5;
    int b  = blockIdx.y;
    int p0 = blockIdx.x * 64;
    int zo = blockIdx.z;                         // oc half: [zo*128, zo*128+128)
    int warpM = wid & 3, warpN = wid >> 2;       // 4M x 2N, warp tile 32oc x 32px
    int ocbase = warpM * 32, nbase = warpN * 32;
    int g = lane >> 2, t = lane & 3;

    const __half* sbh = g_t0h + (size_t)b * HW * 256;
    const __half* gw  = g_w + (size_t)(zo * 128) * 2304;

    // V-prefetch role: thread -> (pixel row, 16B quarter)
    int vpx = tid >> 2, vq = tid & 3;
    int p  = p0 + vpx;
    int y  = p >> 7, x = p & 127;
    // W-prefetch role: thread -> (local oc row, 32B half)
    int wrow = tid >> 1, whalf = tid & 1;

    auto pv = [&](int ch) {
        int kn = ch >> 3;
        int cg = ((ch & 7) << 5) + (vq << 3);
        int ky = kn / 3 - 1, kx = kn - (kn / 3) * 3 - 1;
        int yy = y + ky, xx = x + kx;
        bool valid = ((unsigned)yy < 128u) && ((unsigned)xx < 128u);
        const __half* src = sbh + ((size_t)(valid ? (yy << 7) + xx : 0)) * 256 + cg;
        uint32_t dst = sbase + V0OFF2 + (ch & 3) * V0TILE + vpx * 80 + vq * 16;
        cp16z(dst, src, valid ? 16 : 0);
    };
    auto pw = [&](int ch) {
        const __half* ph = gw + (size_t)wrow * 2304 + ch * 32 + whalf * 16;
        uint32_t dh = sbase + (ch & 3) * W0TILE + wrow * 80 + whalf * 32;
        cp16(dh, ph);
        cp16(dh + 16, ph + 8);
    };

    // prologue: chunks 0 and 1 in flight
    pw(0); pv(0);
    asm volatile("cp.async.commit_group;" ::: "memory");
    pw(1); pv(1);
    asm volatile("cp.async.commit_group;" ::: "memory");

    float acc[2][4][4];
#pragma unroll
    for (int am = 0; am < 2; ++am)
#pragma unroll
        for (int nt = 0; nt < 4; ++nt)
#pragma unroll
            for (int q = 0; q < 4; ++q) acc[am][nt][q] = 0.f;

    int laneoff = (lane & 15) * 80 + (lane >> 4) * 16;

    for (int ch = 0; ch < 72; ++ch) {
        if (ch + 2 < 72) { pw(ch + 2); pv(ch + 2); }
        asm volatile("cp.async.commit_group;" ::: "memory");
        asm volatile("cp.async.wait_group 2;" ::: "memory");
        __syncthreads();

        uint32_t wb = sbase + (ch & 3) * W0TILE;
        uint32_t vb = sbase + V0OFF2 + (ch & 3) * V0TILE;

#pragma unroll
        for (int ks = 0; ks < 2; ++ks) {
            int kb = ks * 32;
            uint32_t B[4][2];
            {
                uint32_t t0, t1, t2, t3;
                ldsm4(vb + (uint32_t)nbase*80 + laneoff + kb, t0, t1, t2, t3);
                B[0][0] = t0; B[1][0] = t1; B[0][1] = t2; B[1][1] = t3;
                ldsm4(vb + (uint32_t)(nbase + 16)*80 + laneoff + kb, t0, t1, t2, t3);
                B[2][0] = t0; B[3][0] = t1; B[2][1] = t2; B[3][1] = t3;
            }
#pragma unroll
            for (int am = 0; am < 2; ++am) {
                uint32_t A[4];
                ldsm4(wb + (uint32_t)(ocbase + am*16)*80 + laneoff + kb,
                      A[0], A[1], A[2], A[3]);
#pragma unroll
                for (int nt = 0; nt < 4; ++nt)
                    mma_fp16(acc[am][nt], A, B[nt]);
            }
        }
    }

#pragma unroll
    for (int am = 0; am < 2; ++am) {
        int oc = zo * 128 + ocbase + am*16 + g;
        float b0 = __ldg(bias + oc);
        float b1 = __ldg(bias + oc + 8);
        float* r0 = outp + ((size_t)(b*256 + oc    ))*HW + p0 + nbase + 2*t;
        float* r1 = outp + ((size_t)(b*256 + oc + 8))*HW + p0 + nbase + 2*t;
#pragma unroll
        for (int nt = 0; nt < 4; ++nt) {
            *(float2*)(r0 + nt*8) = make_float2(acc[am][nt][0] + b0, acc[am][nt][1] + b0);
            *(float2*)(r1 + nt*8) = make_float2(acc[am][nt][2] + b1, acc[am][nt][3] + b1);
        }
    }
}

// ---------------- deform conv (levels 1-3): unchanged from R13 ----------------
#define WSTRIDE 20480
#define VOFF    40960
#define VSTRIDE 5120
#define COFF    51200
#define CWOFF   60416
#define DSMEM_BYTES 69632

__device__ __forceinline__ void prefetch_w(
    uint32_t sbase, const __half* gw, int tid, int chn)
{
    const char* ph = (const char*)(gw + (size_t)tid * 2304 + chn * 32);
    uint32_t dh = sbase + (chn & 1) * WSTRIDE + tid * 80;
#pragma unroll
    for (int u = 0; u < 4; ++u) cp16(dh + u*16, ph + u*16);
}

struct GStage {
    float4 v0, v1, v2, v3;
    float4 w;
    int px;
};

__device__ __forceinline__ void gather_load(
    const char* dsm, const float* __restrict__ sb, int tid, int chn, int iter, GStage& s)
{
    const int4*   sIdx = (const int4*)(dsm + COFF);
    const float4* sWgt = (const float4*)(dsm + CWOFF);
    int kn = chn >> 3;
    const float* bp = sb + ((chn & 7) << 5) + ((tid & 7) << 2);
    s.px = (tid >> 3) + 32 * iter;
    int4 id = sIdx[kn*64 + s.px];
    s.w = sWgt[kn*64 + s.px];
    s.v0 = make_float4(0.f, 0.f, 0.f, 0.f);
    s.v1 = s.v0; s.v2 = s.v0; s.v3 = s.v0;
    if (s.w.x != 0.f) s.v0 = __ldg((const float4*)(bp + id.x));
    if (s.w.y != 0.f) s.v1 = __ldg((const float4*)(bp + id.y));
    if (s.w.z != 0.f) s.v2 = __ldg((const float4*)(bp + id.z));
    if (s.w.w != 0.f) s.v3 = __ldg((const float4*)(bp + id.w));
}

__device__ __forceinline__ void gather_store(
    char* dsm, int tid, int chn, const GStage& s)
{
    char* Vb = dsm + VOFF + (chn & 1) * VSTRIDE;
    float4 a;
    a.x = s.w.x*s.v0.x + s.w.y*s.v1.x + s.w.z*s.v2.x + s.w.w*s.v3.x;
    a.y = s.w.x*s.v0.y + s.w.y*s.v1.y + s.w.z*s.v2.y + s.w.w*s.v3.y;
    a.z = s.w.x*s.v0.z + s.w.y*s.v1.z + s.w.z*s.v2.z + s.w.w*s.v3.z;
    a.w = s.w.x*s.v0.w + s.w.y*s.v1.w + s.w.z*s.v2.w + s.w.w*s.v3.w;
    __half2 h01 = __floats2half2_rn(a.x, a.y);
    __half2 h23 = __floats2half2_rn(a.z, a.w);
    *(uint2*)(Vb + s.px * 80 + (tid & 7) * 8) =
        make_uint2(*(uint32_t*)&h01, *(uint32_t*)&h23);
}

__global__ __launch_bounds__(256, 2) void k_dconv_mma(
    int level, const float* __restrict__ off_b_lvl,
    const float* __restrict__ bias, float* __restrict__ outp, int HW, int Wc,
    int nch, int use_part)
{
    extern __shared__ char dsm[];
    uint32_t sbase = smem_u32(dsm);

    int tid = threadIdx.x;
    int lane = tid & 31, wid = tid >> 5;
    int b  = blockIdx.y;
    int p0 = blockIdx.x * 64;
    int ks0 = blockIdx.z * nch;
    int warpM = wid & 3, warpN = wid >> 2;
    int ocbase = warpM * 64, nbase = warpN * 32;
    int g = lane >> 2, t = lane & 3;

    const float* sb = t_buf(level) + (size_t)b * HW * 256 + (size_t)p0 * 256;
    const __half* gw = g_w + (size_t)level * 256 * 2304;

    prefetch_w(sbase, gw, tid, ks0);
    asm volatile("cp.async.commit_group;" ::: "memory");

    // ---- fused coefficient prologue (offreduce + bilinear coef) ----
    int4*   sIdx = (int4*)(dsm + COFF);
    float4* sWgt = (float4*)(dsm + CWOFF);
    float fH = (float)((HW / Wc) - 1), fW = (float)(Wc - 1);
    for (int i = tid; i < 576; i += 256) {
        int k = i >> 6, px = i & 63;
        int p = p0 + px;
        int y = p / Wc, x = p % Wc;
        float dy = __ldg(off_b_lvl + 2*k);
        float dx = __ldg(off_b_lvl + 2*k + 1);
        size_t basei  = ((size_t)(b*18 + 2*k))*HW + p;
        size_t stride = (size_t)8*18*HW;
#pragma unroll
        for (int cs = 0; cs < 8; ++cs) {
            dy += g_offp[(size_t)cs*stride + basei];
            dx += g_offp[(size_t)cs*stride + basei + HW];
        }
        float py = (float)(y + k/3 - 1) + dy;
        float px_f = (float)(x + (k%3) - 1) + dx;
        float y0 = floorf(py), x0 = floorf(px_f);
        float ly = py - y0, lx = px_f - x0;
        int id[4]; float wv[4];
#pragma unroll
        for (int q = 0; q < 4; ++q) {
            float yf = y0 + (float)(q >> 1);
            float xf = x0 + (float)(q & 1);
            float wy = (q >> 1) ? ly : 1.f - ly;
            float wx = (q & 1)  ? lx : 1.f - lx;
            bool v = (yf >= 0.f) && (yf <= fH) && (xf >= 0.f) && (xf <= fW);
            float yc = fminf(fmaxf(yf, 0.f), fH);
            float xc = fminf(fmaxf(xf, 0.f), fW);
            id[q] = (((int)yc * Wc + (int)xc) - p0) * 256;   // relative to sb
            wv[q] = v ? wy * wx : 0.f;
        }
        sIdx[i] = make_int4(id[0], id[1], id[2], id[3]);
        sWgt[i] = make_float4(wv[0], wv[1], wv[2], wv[3]);
    }
    __syncthreads();

    {
        GStage s0, s1;
        gather_load((const char*)dsm, sb, tid, ks0, 0, s0);
        gather_load((const char*)dsm, sb, tid, ks0, 1, s1);
        gather_store(dsm, tid, ks0, s0);
        gather_store(dsm, tid, ks0, s1);
    }
    asm volatile("cp.async.wait_group 0;" ::: "memory");
    __syncthreads();

    float acc[4][4][4];
#pragma unroll
    for (int mt = 0; mt < 4; ++mt)
#pragma unroll
        for (int nt = 0; nt < 4; ++nt)
#pragma unroll
            for (int q = 0; q < 4; ++q) acc[mt][nt][q] = 0.f;

    int laneoff = (lane & 15) * 80 + (lane >> 4) * 16;
    int kend = ks0 + nch;

    for (int ch = ks0; ch < kend; ++ch) {
        uint32_t wb = sbase + (ch & 1) * WSTRIDE;
        uint32_t vb = sbase + VOFF + (ch & 1) * VSTRIDE;
        bool pre = (ch + 1 < kend);

        if (pre) prefetch_w(sbase, gw, tid, ch + 1);
        asm volatile("cp.async.commit_group;" ::: "memory");

        GStage s0, s1;
        if (pre) {
            gather_load((const char*)dsm, sb, tid, ch + 1, 0, s0);
            gather_load((const char*)dsm, sb, tid, ch + 1, 1, s1);
        }

        {
            int kb = 0;
            uint32_t B[4][2];
            {
                uint32_t t0, t1, t2, t3;
                ldsm4(vb + (uint32_t)nbase*80 + laneoff + kb, t0, t1, t2, t3);
                B[0][0] = t0; B[1][0] = t1; B[0][1] = t2; B[1][1] = t3;
                ldsm4(vb + (uint32_t)(nbase + 16)*80 + laneoff + kb, t0, t1, t2, t3);
                B[2][0] = t0; B[3][0] = t1; B[2][1] = t2; B[3][1] = t3;
            }
#pragma unroll
            for (int mt = 0; mt < 4; ++mt) {
                uint32_t A[4];
                ldsm4(wb + (uint32_t)(ocbase + mt*16)*80 + laneoff + kb,
                      A[0], A[1], A[2], A[3]);
#pragma unroll
                for (int nt = 0; nt < 4; ++nt)
                    mma_fp16(acc[mt][nt], A, B[nt]);
            }
        }

        if (pre) gather_store(dsm, tid, ch + 1, s0);

        {
            int kb = 32;
            uint32_t B[4][2];
            {
                uint32_t t0, t1, t2, t3;
                ldsm4(vb + (uint32_t)nbase*80 + laneoff + kb, t0, t1, t2, t3);
                B[0][0] = t0; B[1][0] = t1; B[0][1] = t2; B[1][1] = t3;
                ldsm4(vb + (uint32_t)(nbase + 16)*80 + laneoff + kb, t0, t1, t2, t3);
                B[2][0] = t0; B[3][0] = t1; B[2][1] = t2; B[3][1] = t3;
            }
#pragma unroll
            for (int mt = 0; mt < 4; ++mt) {
                uint32_t A[4];
                ldsm4(wb + (uint32_t)(ocbase + mt*16)*80 + laneoff + kb,
                      A[0], A[1], A[2], A[3]);
#pragma unroll
                for (int nt = 0; nt < 4; ++nt)
                    mma_fp16(acc[mt][nt], A, B[nt]);
            }
        }

        if (pre) gather_store(dsm, tid, ch + 1, s1);

        asm volatile("cp.async.wait_group 0;" ::: "memory");
        __syncthreads();
    }

    if (use_part) {
        float* pp = g_part + (size_t)blockIdx.z * 8 * 256 * HW;
#pragma unroll
        for (int mt = 0; mt < 4; ++mt) {
            int oc = ocbase + mt*16 + g;
            float* r0 = pp + ((size_t)(b*256 + oc    ))*HW + p0 + nbase + 2*t;
            float* r1 = pp + ((size_t)(b*256 + oc + 8))*HW + p0 + nbase + 2*t;
#pragma unroll
            for (int nt = 0; nt < 4; ++nt) {
                *(float2*)(r0 + nt*8) = make_float2(acc[mt][nt][0], acc[mt][nt][1]);
                *(float2*)(r1 + nt*8) = make_float2(acc[mt][nt][2], acc[mt][nt][3]);
            }
        }
    } else {
#pragma unroll
        for (int mt = 0; mt < 4; ++mt) {
            int oc = ocbase + mt*16 + g;
            float b0 = __ldg(bias + oc);
            float b1 = __ldg(bias + oc + 8);
            float* r0 = outp + ((size_t)(b*256 + oc    ))*HW + p0 + nbase + 2*t;
            float* r1 = outp + ((size_t)(b*256 + oc + 8))*HW + p0 + nbase + 2*t;
#pragma unroll
            for (int nt = 0; nt < 4; ++nt) {
                *(float2*)(r0 + nt*8) = make_float2(acc[mt][nt][0] + b0, acc[mt][nt][1] + b0);
                *(float2*)(r1 + nt*8) = make_float2(acc[mt][nt][2] + b1, acc[mt][nt][3] + b1);
            }
        }
    }
}

// ---------------- host side ----------------
static inline int divup(int a, int b) { return (a + b - 1) / b; }

extern "C" void kernel_launch(void* const* d_in, const int* in_sizes, int n_in,
                              void* d_out, int out_size) {
    const float* x0      = (const float*)d_in[0];
    const float* x1      = (const float*)d_in[1];
    const float* x2      = (const float*)d_in[2];
    const float* x3      = (const float*)d_in[3];
    const float* weights = (const float*)d_in[4];
    const float* biases  = (const float*)d_in[5];
    const float* off_w   = (const float*)d_in[6];
    const float* off_b   = (const float*)d_in[7];
    float* out = (float*)d_out;

    const size_t T0 = 0;
    const size_t T1 = 33554432;
    const size_t T2 = 41943040;
    const size_t T3 = 44040192;

    (void)in_sizes; (void)n_in; (void)out_size;

    cudaFuncSetAttribute(k_dconv_mma, cudaFuncAttributeMaxDynamicSharedMemorySize, DSMEM_BYTES);
    cudaFuncSetAttribute(k_conv0, cudaFuncAttributeMaxDynamicSharedMemorySize, DSMEM0);

    k_prep<<<divup(4*256*2304, 256), 256>>>(weights, off_w);

    // ---- level 3 (16x16): K-split 8 ----
    {
        int H = 16, W = 16, hw = 256, S = 8;
        k_fuse_t<<<dim3(hw/32, 8, 8), 256>>>(x3, nullptr, 3, W, hw);
        k_offconv<<<dim3(divup(8*hw, 128), 8), 128>>>(x3, 3, H, W);
        k_dconv_mma<<<dim3(hw/64, 8, S), 256, DSMEM_BYTES>>>(3, off_b + 3*18,
                                                             nullptr, nullptr, hw, W, 72/S, 1);
        k_reduce<<<divup(8*256*hw/4, 256), 256>>>(biases + 3*256, out + T3, hw, S);
    }
    // ---- level 2 (32x32): K-split 4 ----
    {
        int H = 32, W = 32, hw = 1024, S = 4;
        k_fuse_t<<<dim3(hw/32, 8, 8), 256>>>(x2, out + T3, 2, W, hw);
        k_offconv<<<dim3(divup(8*hw, 128), 8), 128>>>(nullptr, 2, H, W);
        k_dconv_mma<<<dim3(hw/64, 8, S), 256, DSMEM_BYTES>>>(2, off_b + 2*18,
                                                             nullptr, nullptr, hw, W, 72/S, 1);
        k_reduce<<<divup(8*256*hw/4, 256), 256>>>(biases + 2*256, out + T2, hw, S);
    }
    // ---- level 1 (64x64): no split ----
    {
        int H = 64, W = 64, hw = 4096;
        k_fuse_t<<<dim3(hw/32, 8, 8), 256>>>(x1, out + T2, 1, W, hw);
        k_offconv<<<dim3(divup(8*hw, 128), 8), 128>>>(nullptr, 1, H, W);
        k_dconv_mma<<<dim3(hw/64, 8, 1), 256, DSMEM_BYTES>>>(1, off_b + 1*18,
                                                             biases + 256, out + T1, hw, W, 72, 0);
    }
    // ---- level 0 (128x128): 128oc-tile plain conv, 4-buffer pipeline, 3 blocks/SM ----
    {
        int hw = 16384;
        k_fuse_t<<<dim3(hw/32, 8, 8), 256>>>(x0, out + T1, 0, 128, hw);
        k_conv0<<<dim3(hw/64, 8, 2), 256, DSMEM0>>>(biases, out + T0);
    }
}